// round 2
// baseline (speedup 1.0000x reference)
#include <cuda_runtime.h>
#include <math.h>

#define EMBED 512
#define NBATCH 8
#define QLEN 2048
#define KLEN 4096

// ---------------- scratch (device globals; no allocation) ----------------
__device__ float d_Qm[NBATCH * QLEN * EMBED];                 //  32 MB
__device__ float d_Km[NBATCH * KLEN * EMBED];                 //  64 MB
__device__ float d_Vm[NBATCH * KLEN * EMBED];                 //  64 MB
__device__ float d_E [(size_t)NBATCH * QLEN * KLEN];          // 256 MB
__device__ float d_O [NBATCH * QLEN * EMBED];                 //  32 MB

// ---------------- tiled SGEMM: C = A * op(B) (+ resid + bias) ------------
// A: [M,K] row-major. TRANSB: B is [N,K] row-major (compute A@B^T).
// !TRANSB: B is [K,N] row-major. Batched via blockIdx.z with ll strides.
// Requires M%128==0, N%128==0, K%16==0 (true for all calls here).
template <bool TRANSB, bool EPI>
__global__ void __launch_bounds__(256, 1)
sgemm_kernel(const float* __restrict__ A, const float* __restrict__ B,
             float* __restrict__ C, int M, int N, int K,
             long long sA, long long sB, long long sC,
             const float* __restrict__ resid, const float* __restrict__ bias)
{
    constexpr int BM = 128, BN = 128, BK = 16;
    __shared__ float As[BK][BM];
    __shared__ float Bs[BK][BN];

    const int b = blockIdx.z;
    A += (long long)b * sA;
    B += (long long)b * sB;
    C += (long long)b * sC;
    if (EPI) resid += (long long)b * sC;

    const int m0 = blockIdx.y * BM;
    const int n0 = blockIdx.x * BN;
    const int t  = threadIdx.x;

    const int tx = t & 15;         // 0..15
    const int ty = t >> 4;         // 0..15
    const int rowBase = ty * 8;
    const int colBase = tx * 8;

    float acc[8][8] = {};

    for (int k0 = 0; k0 < K; k0 += BK) {
        // ---- load A tile (BM x BK), store transposed into As[k][m] ----
        #pragma unroll
        for (int it = 0; it < 2; it++) {
            int idx = t + it * 256;          // 0..511 float4s
            int m   = idx >> 2;              // 0..127
            int k4  = (idx & 3) * 4;         // 0,4,8,12
            float4 v = *reinterpret_cast<const float4*>(
                &A[(long long)(m0 + m) * K + k0 + k4]);
            As[k4 + 0][m] = v.x; As[k4 + 1][m] = v.y;
            As[k4 + 2][m] = v.z; As[k4 + 3][m] = v.w;
        }
        // ---- load B tile into Bs[k][n] ----
        if (TRANSB) {
            #pragma unroll
            for (int it = 0; it < 2; it++) {
                int idx = t + it * 256;
                int n   = idx >> 2;
                int k4  = (idx & 3) * 4;
                float4 v = *reinterpret_cast<const float4*>(
                    &B[(long long)(n0 + n) * K + k0 + k4]);
                Bs[k4 + 0][n] = v.x; Bs[k4 + 1][n] = v.y;
                Bs[k4 + 2][n] = v.z; Bs[k4 + 3][n] = v.w;
            }
        } else {
            #pragma unroll
            for (int it = 0; it < 2; it++) {
                int idx = t + it * 256;
                int k   = idx >> 5;              // 0..15
                int n4  = (idx & 31) * 4;        // 0..124
                float4 v = *reinterpret_cast<const float4*>(
                    &B[(long long)(k0 + k) * N + n0 + n4]);
                *reinterpret_cast<float4*>(&Bs[k][n4]) = v;
            }
        }
        __syncthreads();

        // ---- 8x8 register-tile FMA ----
        #pragma unroll
        for (int k = 0; k < BK; k++) {
            float ra[8], rb[8];
            #pragma unroll
            for (int i = 0; i < 8; i++) ra[i] = As[k][rowBase + i];
            #pragma unroll
            for (int j = 0; j < 8; j++) rb[j] = Bs[k][colBase + j];
            #pragma unroll
            for (int i = 0; i < 8; i++)
                #pragma unroll
                for (int j = 0; j < 8; j++)
                    acc[i][j] += ra[i] * rb[j];
        }
        __syncthreads();
    }

    // ---- epilogue / store ----
    #pragma unroll
    for (int i = 0; i < 8; i++) {
        const int m = m0 + rowBase + i;
        #pragma unroll
        for (int j = 0; j < 8; j += 4) {
            const int n = n0 + colBase + j;
            float4 v;
            v.x = acc[i][j + 0]; v.y = acc[i][j + 1];
            v.z = acc[i][j + 2]; v.w = acc[i][j + 3];
            if (EPI) {
                float4 r = *reinterpret_cast<const float4*>(
                    &resid[(long long)m * N + n]);
                float4 bb = *reinterpret_cast<const float4*>(&bias[n]);
                v.x += r.x + bb.x; v.y += r.y + bb.y;
                v.z += r.z + bb.z; v.w += r.w + bb.w;
            }
            *reinterpret_cast<float4*>(&C[(long long)m * N + n]) = v;
        }
    }
}

// ---------------- row softmax over K=4096 with scale 1/sqrt(512) ---------
__inline__ __device__ float warpMax(float v) {
    #pragma unroll
    for (int o = 16; o; o >>= 1) v = fmaxf(v, __shfl_xor_sync(0xffffffffu, v, o));
    return v;
}
__inline__ __device__ float warpSum(float v) {
    #pragma unroll
    for (int o = 16; o; o >>= 1) v += __shfl_xor_sync(0xffffffffu, v, o);
    return v;
}

__global__ void __launch_bounds__(256, 1)
softmax_rows(float* __restrict__ E)
{
    const long long row = blockIdx.x;
    float4* p4 = reinterpret_cast<float4*>(E + row * KLEN);
    const int t = threadIdx.x;
    const float scale = rsqrtf((float)EMBED);

    __shared__ float red[8];

    float4 v[4];
    float mx = -INFINITY;
    #pragma unroll
    for (int i = 0; i < 4; i++) {
        float4 x = p4[t + i * 256];
        x.x *= scale; x.y *= scale; x.z *= scale; x.w *= scale;
        v[i] = x;
        mx = fmaxf(mx, fmaxf(fmaxf(x.x, x.y), fmaxf(x.z, x.w)));
    }
    mx = warpMax(mx);
    if ((t & 31) == 0) red[t >> 5] = mx;
    __syncthreads();
    if (t < 32) {
        float m = (t < 8) ? red[t] : -INFINITY;
        m = warpMax(m);
        if (t == 0) red[0] = m;
    }
    __syncthreads();
    mx = red[0];

    float sum = 0.f;
    #pragma unroll
    for (int i = 0; i < 4; i++) {
        v[i].x = expf(v[i].x - mx); v[i].y = expf(v[i].y - mx);
        v[i].z = expf(v[i].z - mx); v[i].w = expf(v[i].w - mx);
        sum += v[i].x + v[i].y + v[i].z + v[i].w;
    }
    sum = warpSum(sum);
    __syncthreads();
    if ((t & 31) == 0) red[t >> 5] = sum;
    __syncthreads();
    if (t < 32) {
        float s = (t < 8) ? red[t] : 0.f;
        s = warpSum(s);
        if (t == 0) red[0] = s;
    }
    __syncthreads();
    const float inv = 1.f / red[0];

    #pragma unroll
    for (int i = 0; i < 4; i++) {
        v[i].x *= inv; v[i].y *= inv; v[i].z *= inv; v[i].w *= inv;
        p4[t + i * 256] = v[i];
    }
}

// ---------------- launch -------------------------------------------------
extern "C" void kernel_launch(void* const* d_in, const int* in_sizes, int n_in,
                              void* d_out, int out_size)
{
    const float* x  = (const float*)d_in[0];   // [8,2048,512]
    const float* y  = (const float*)d_in[1];   // [8,4096,512]
    const float* Wq = (const float*)d_in[2];   // [512,512]
    const float* Wk = (const float*)d_in[3];
    const float* Wv = (const float*)d_in[4];
    const float* Wo = (const float*)d_in[5];
    const float* bo = (const float*)d_in[6];   // [512]
    float* out = (float*)d_out;                // [8,2048,512]

    float *Qm, *Km, *Vm, *E, *O;
    cudaGetSymbolAddress((void**)&Qm, d_Qm);
    cudaGetSymbolAddress((void**)&Km, d_Km);
    cudaGetSymbolAddress((void**)&Vm, d_Vm);
    cudaGetSymbolAddress((void**)&E,  d_E);
    cudaGetSymbolAddress((void**)&O,  d_O);

    const int MQ = NBATCH * QLEN;  // 16384
    const int MK = NBATCH * KLEN;  // 32768

    // 1-3: projections  (A @ W^T)
    sgemm_kernel<true, false><<<dim3(EMBED / 128, MQ / 128, 1), 256>>>(
        x, Wq, Qm, MQ, EMBED, EMBED, 0, 0, 0, nullptr, nullptr);
    sgemm_kernel<true, false><<<dim3(EMBED / 128, MK / 128, 1), 256>>>(
        y, Wk, Km, MK, EMBED, EMBED, 0, 0, 0, nullptr, nullptr);
    sgemm_kernel<true, false><<<dim3(EMBED / 128, MK / 128, 1), 256>>>(
        y, Wv, Vm, MK, EMBED, EMBED, 0, 0, 0, nullptr, nullptr);

    // 4: energy E_n = Qm_n @ Km_n^T   [2048 x 4096], batched over 8
    sgemm_kernel<true, false><<<dim3(KLEN / 128, QLEN / 128, NBATCH), 256>>>(
        Qm, Km, E, QLEN, KLEN, EMBED,
        (long long)QLEN * EMBED, (long long)KLEN * EMBED,
        (long long)QLEN * KLEN, nullptr, nullptr);

    // 5: softmax rows (scale 1/sqrt(512) applied inside)
    softmax_rows<<<NBATCH * QLEN, 256>>>(E);

    // 6: O_n = A_n @ Vm_n   [2048 x 512], K=4096, batched
    sgemm_kernel<false, false><<<dim3(EMBED / 128, QLEN / 128, NBATCH), 256>>>(
        E, Vm, O, QLEN, EMBED, KLEN,
        (long long)QLEN * KLEN, (long long)KLEN * EMBED,
        (long long)QLEN * EMBED, nullptr, nullptr);

    // 7: out = x + O @ Wo^T + bo
    sgemm_kernel<true, true><<<dim3(EMBED / 128, MQ / 128, 1), 256>>>(
        O, Wo, out, MQ, EMBED, EMBED, 0, 0, 0, x, bo);
}

// round 4
// speedup vs baseline: 2.4601x; 2.4601x over previous
#include <cuda_runtime.h>
#include <cuda_bf16.h>
#include <stdint.h>
#include <math.h>

#define EMBED 512
#define NBATCH 8
#define QLEN 2048
#define KLEN 4096
#define MQ (NBATCH*QLEN)
#define MK (NBATCH*KLEN)
typedef __nv_bfloat16 bf16;

// ---------------- device scratch ----------------
__device__ bf16 g_xhi[MQ*EMBED],  g_xlo[MQ*EMBED];
__device__ bf16 g_yhi[MK*EMBED],  g_ylo[MK*EMBED];
__device__ bf16 g_Wqhi[EMBED*EMBED], g_Wqlo[EMBED*EMBED];
__device__ bf16 g_Wkhi[EMBED*EMBED], g_Wklo[EMBED*EMBED];
__device__ bf16 g_Wvhi[EMBED*EMBED], g_Wvlo[EMBED*EMBED];
__device__ bf16 g_Wohi[EMBED*EMBED], g_Wolo[EMBED*EMBED];
__device__ bf16 g_Qhi[MQ*EMBED],  g_Qlo[MQ*EMBED];
__device__ bf16 g_Khi[MK*EMBED],  g_Klo[MK*EMBED];
__device__ bf16 g_Vnhi[MK*EMBED], g_Vnlo[MK*EMBED];
__device__ bf16 g_Vthi[(size_t)NBATCH*EMBED*KLEN], g_Vtlo[(size_t)NBATCH*EMBED*KLEN];
__device__ bf16 g_Ehi[(size_t)MQ*KLEN], g_Elo[(size_t)MQ*KLEN];
__device__ bf16 g_Ohi[MQ*EMBED],  g_Olo[MQ*EMBED];

// ---------------- helpers ----------------
__device__ __forceinline__ uint32_t smem_u32(const void* p){
    uint32_t a;
    asm("{ .reg .u64 t; cvta.to.shared.u64 t, %1; cvt.u32.u64 %0, t; }" : "=r"(a) : "l"(p));
    return a;
}
#define CP16(s,g)   asm volatile("cp.async.cg.shared.global [%0], [%1], 16;" :: "r"(s), "l"(g) : "memory")
#define CP_COMMIT() asm volatile("cp.async.commit_group;" ::: "memory")
#define CP_WAIT1()  asm volatile("cp.async.wait_group 1;" ::: "memory")
#define CP_WAIT0()  asm volatile("cp.async.wait_group 0;" ::: "memory")

__device__ __forceinline__ void ldm4(uint32_t* r, uint32_t a){
    asm volatile("ldmatrix.sync.aligned.m8n8.x4.shared.b16 {%0,%1,%2,%3}, [%4];"
        : "=r"(r[0]), "=r"(r[1]), "=r"(r[2]), "=r"(r[3]) : "r"(a));
}
__device__ __forceinline__ void mma_bf16(float* c, const uint32_t* a, const uint32_t* b){
    asm volatile("mma.sync.aligned.m16n8k16.row.col.f32.bf16.bf16.f32 "
        "{%0,%1,%2,%3}, {%4,%5,%6,%7}, {%8,%9}, {%0,%1,%2,%3};"
        : "+f"(c[0]), "+f"(c[1]), "+f"(c[2]), "+f"(c[3])
        : "r"(a[0]), "r"(a[1]), "r"(a[2]), "r"(a[3]), "r"(b[0]), "r"(b[1]));
}
__device__ __forceinline__ uint32_t pack2(float x, float y){
    __nv_bfloat162 t = __halves2bfloat162(__float2bfloat16(x), __float2bfloat16(y));
    return *reinterpret_cast<uint32_t*>(&t);
}

// ---------------- split-bf16 3-term mma.sync GEMM ----------------
// D[m][n] = sum_k A[m][k]*B[n][k], A=Ah+Al, B=Bh+Bl (drop AlBl).
// Tile 128x128x32, 256 thr (8 warps: 4 over m x 2 over n; warp = 32m x 64n).
// EPI 0: write split bf16 Chi/Clo. EPI 2: f32 out = acc + resid + bias.
#define GSMEM (2*32768 + 1024)

template<int EPI>
__global__ void __launch_bounds__(256, 1)
gemm3(const bf16* __restrict__ Ahi, const bf16* __restrict__ Alo, long long sA, int lda,
      const bf16* __restrict__ Bhi, const bf16* __restrict__ Blo, long long sB, int ldb,
      int Kdim,
      bf16* __restrict__ Chi, bf16* __restrict__ Clo, long long sC, int ldc,
      float* __restrict__ Cf, const float* __restrict__ resid, const float* __restrict__ bias)
{
    extern __shared__ char dynsm[];
    const uint32_t tiles = (smem_u32(dynsm) + 1023u) & ~1023u;
    const int tid = threadIdx.x, lane = tid & 31, wid = tid >> 5;
    const int wm = wid & 3, wn = wid >> 2;
    const int m0 = blockIdx.y * 128, n0 = blockIdx.x * 128, b = blockIdx.z;
    Ahi += (size_t)b * sA;  Alo += (size_t)b * sA;
    Bhi += (size_t)b * sB;  Blo += (size_t)b * sB;
    if (EPI == 0) { Chi += (size_t)b * sC; Clo += (size_t)b * sC; }

    float acc[2][8][4];
    #pragma unroll
    for (int i = 0; i < 2; i++)
        #pragma unroll
        for (int j = 0; j < 8; j++)
            #pragma unroll
            for (int k = 0; k < 4; k++) acc[i][j][k] = 0.f;

    // ldmatrix lane addressing (swizzle: chunk ^= (row>>1)&3, 16B chunks, 64B rows)
    const int r_lane = (lane & 7) + ((lane >> 3) & 1) * 8;
    uint32_t aRow[2], aSw[2];
    #pragma unroll
    for (int mt = 0; mt < 2; mt++){
        int m_loc = wm * 32 + mt * 16 + r_lane;
        aRow[mt] = (uint32_t)(m_loc * 64);
        aSw[mt]  = (uint32_t)((m_loc >> 1) & 3);
    }
    const uint32_t aCk = (lane >> 4) & 1;
    uint32_t bRow[4], bSw[4];
    {
        int n_base = wn * 64 + ((lane >> 4) & 1) * 8 + (lane & 7);
        #pragma unroll
        for (int g = 0; g < 4; g++){
            int n_loc = n_base + g * 16;
            bRow[g] = (uint32_t)(n_loc * 64);
            bSw[g]  = (uint32_t)((n_loc >> 1) & 3);
        }
    }
    const uint32_t bCk = (lane >> 3) & 1;

    const int C = Kdim >> 5;

    auto load_chunk = [&](int c){
        const uint32_t sb = tiles + (c & 1) * 32768;
        const int k0 = c << 5;
        #pragma unroll
        for (int half = 0; half < 2; half++){
            int row = (tid >> 2) + half * 64;
            int ch  = tid & 3;
            uint32_t so = (uint32_t)(row * 64 + ((ch ^ ((row >> 1) & 3)) << 4));
            size_t ga = (size_t)(m0 + row) * lda + k0 + ch * 8;
            size_t gb = (size_t)(n0 + row) * ldb + k0 + ch * 8;
            CP16(sb +         so, Ahi + ga);
            CP16(sb +  8192 + so, Alo + ga);
            CP16(sb + 16384 + so, Bhi + gb);
            CP16(sb + 24576 + so, Blo + gb);
        }
    };

    load_chunk(0); CP_COMMIT();

    for (int c = 0; c < C; c++){
        if (c + 1 < C){ load_chunk(c + 1); CP_COMMIT(); CP_WAIT1(); }
        else          { CP_WAIT0(); }
        __syncthreads();

        const uint32_t sb = tiles + (c & 1) * 32768;
        #pragma unroll
        for (int ks = 0; ks < 2; ks++){
            uint32_t ah[2][4], al[2][4];
            #pragma unroll
            for (int mt = 0; mt < 2; mt++){
                uint32_t off = aRow[mt] + ((((uint32_t)(2 * ks) + aCk) ^ aSw[mt]) << 4);
                ldm4(ah[mt], sb + off);
                ldm4(al[mt], sb + 8192 + off);
            }
            uint32_t bh[8][2], bl[8][2];
            #pragma unroll
            for (int g = 0; g < 4; g++){
                uint32_t off = bRow[g] + ((((uint32_t)(2 * ks) + bCk) ^ bSw[g]) << 4);
                uint32_t q[4];
                ldm4(q, sb + 16384 + off);
                bh[2*g][0]=q[0]; bh[2*g][1]=q[1]; bh[2*g+1][0]=q[2]; bh[2*g+1][1]=q[3];
                ldm4(q, sb + 24576 + off);
                bl[2*g][0]=q[0]; bl[2*g][1]=q[1]; bl[2*g+1][0]=q[2]; bl[2*g+1][1]=q[3];
            }
            #pragma unroll
            for (int mt = 0; mt < 2; mt++)
                #pragma unroll
                for (int nf = 0; nf < 8; nf++){
                    mma_bf16(acc[mt][nf], ah[mt], bh[nf]);
                    mma_bf16(acc[mt][nf], ah[mt], bl[nf]);
                    mma_bf16(acc[mt][nf], al[mt], bh[nf]);
                }
        }
        __syncthreads();
    }

    // ---------------- epilogue ----------------
    const int er = lane >> 2, ec = (lane & 3) * 2;
    #pragma unroll
    for (int mt = 0; mt < 2; mt++)
        #pragma unroll
        for (int nf = 0; nf < 8; nf++){
            const int n = n0 + wn * 64 + nf * 8 + ec;
            #pragma unroll
            for (int rr = 0; rr < 2; rr++){
                const int m = m0 + wm * 32 + mt * 16 + er + rr * 8;
                float v0 = acc[mt][nf][rr * 2], v1 = acc[mt][nf][rr * 2 + 1];
                if (EPI == 0){
                    bf16 h0 = __float2bfloat16(v0), h1 = __float2bfloat16(v1);
                    float l0 = v0 - __bfloat162float(h0), l1 = v1 - __bfloat162float(h1);
                    __nv_bfloat162 hp = __halves2bfloat162(h0, h1);
                    __nv_bfloat162 lp = __halves2bfloat162(__float2bfloat16(l0), __float2bfloat16(l1));
                    *reinterpret_cast<uint32_t*>(Chi + (size_t)m * ldc + n) = *reinterpret_cast<uint32_t*>(&hp);
                    *reinterpret_cast<uint32_t*>(Clo + (size_t)m * ldc + n) = *reinterpret_cast<uint32_t*>(&lp);
                } else {
                    size_t off = (size_t)m * ldc + n;
                    float2 rv = *reinterpret_cast<const float2*>(resid + off);
                    float2 bv = *reinterpret_cast<const float2*>(bias + n);
                    float2 o; o.x = v0 + rv.x + bv.x; o.y = v1 + rv.y + bv.y;
                    *reinterpret_cast<float2*>(Cf + off) = o;
                }
            }
        }
}

// ---------------- f32 -> bf16 hi/lo split ----------------
__global__ void __launch_bounds__(256, 1)
split_f32(const float* __restrict__ in, bf16* __restrict__ hi, bf16* __restrict__ lo, int n)
{
    int i = (blockIdx.x * 256 + threadIdx.x) * 4;
    if (i >= n) return;
    float4 v = *reinterpret_cast<const float4*>(in + i);
    __align__(8) bf16 h[4], l[4];
    h[0]=__float2bfloat16(v.x); l[0]=__float2bfloat16(v.x-__bfloat162float(h[0]));
    h[1]=__float2bfloat16(v.y); l[1]=__float2bfloat16(v.y-__bfloat162float(h[1]));
    h[2]=__float2bfloat16(v.z); l[2]=__float2bfloat16(v.z-__bfloat162float(h[2]));
    h[3]=__float2bfloat16(v.w); l[3]=__float2bfloat16(v.w-__bfloat162float(h[3]));
    *reinterpret_cast<uint2*>(hi + i) = *reinterpret_cast<const uint2*>(h);
    *reinterpret_cast<uint2*>(lo + i) = *reinterpret_cast<const uint2*>(l);
}

// ---------------- V transpose: [b][kk][d] -> [b][d][kk], hi+lo ----------------
__global__ void __launch_bounds__(256, 1)
transposeV(const bf16* __restrict__ Ah, const bf16* __restrict__ Al,
           bf16* __restrict__ Th, bf16* __restrict__ Tl)
{
    __shared__ bf16 sh[32][33], sl[32][33];
    const int b = blockIdx.z, kk0 = blockIdx.x * 32, d0 = blockIdx.y * 32;
    const int tx = threadIdx.x & 31, ty = threadIdx.x >> 5;
    const bf16* ah = Ah + (size_t)b * KLEN * EMBED;
    const bf16* al = Al + (size_t)b * KLEN * EMBED;
    #pragma unroll
    for (int i = ty; i < 32; i += 8){
        sh[i][tx] = ah[(size_t)(kk0 + i) * EMBED + d0 + tx];
        sl[i][tx] = al[(size_t)(kk0 + i) * EMBED + d0 + tx];
    }
    __syncthreads();
    bf16* th = Th + (size_t)b * EMBED * KLEN;
    bf16* tl = Tl + (size_t)b * EMBED * KLEN;
    #pragma unroll
    for (int i = ty; i < 32; i += 8){
        th[(size_t)(d0 + i) * KLEN + kk0 + tx] = sh[tx][i];
        tl[(size_t)(d0 + i) * KLEN + kk0 + tx] = sl[tx][i];
    }
}

// ---------------- softmax on split rows, in place ----------------
__inline__ __device__ float wmax(float v){
    #pragma unroll
    for (int o = 16; o; o >>= 1) v = fmaxf(v, __shfl_xor_sync(0xffffffffu, v, o));
    return v;
}
__inline__ __device__ float wsum(float v){
    #pragma unroll
    for (int o = 16; o; o >>= 1) v += __shfl_xor_sync(0xffffffffu, v, o);
    return v;
}
__global__ void __launch_bounds__(256, 1)
softmax_split(bf16* __restrict__ Eh, bf16* __restrict__ El)
{
    const size_t base = (size_t)blockIdx.x * KLEN;
    const int t = threadIdx.x;
    const float scale = rsqrtf((float)EMBED);
    __shared__ float red[8];

    float v[16];
    #pragma unroll
    for (int i = 0; i < 2; i++){
        uint4 hu = *reinterpret_cast<const uint4*>(Eh + base + (size_t)(t + i*256) * 8);
        uint4 lu = *reinterpret_cast<const uint4*>(El + base + (size_t)(t + i*256) * 8);
        const bf16* hp = reinterpret_cast<const bf16*>(&hu);
        const bf16* lp = reinterpret_cast<const bf16*>(&lu);
        #pragma unroll
        for (int k = 0; k < 8; k++)
            v[i*8+k] = (__bfloat162float(hp[k]) + __bfloat162float(lp[k])) * scale;
    }
    float mx = -INFINITY;
    #pragma unroll
    for (int i = 0; i < 16; i++) mx = fmaxf(mx, v[i]);
    mx = wmax(mx);
    if ((t & 31) == 0) red[t >> 5] = mx;
    __syncthreads();
    if (t < 32){ float m = (t < 8) ? red[t] : -INFINITY; m = wmax(m); if (!t) red[0] = m; }
    __syncthreads();
    mx = red[0];
    __syncthreads();
    float sum = 0.f;
    #pragma unroll
    for (int i = 0; i < 16; i++){ v[i] = __expf(v[i] - mx); sum += v[i]; }
    sum = wsum(sum);
    if ((t & 31) == 0) red[t >> 5] = sum;
    __syncthreads();
    if (t < 32){ float s = (t < 8) ? red[t] : 0.f; s = wsum(s); if (!t) red[0] = s; }
    __syncthreads();
    const float inv = 1.f / red[0];
    #pragma unroll
    for (int i = 0; i < 2; i++){
        __align__(16) bf16 hb[8], lb[8];
        #pragma unroll
        for (int k = 0; k < 8; k++){
            float p = v[i*8+k] * inv;
            bf16 h = __float2bfloat16(p);
            hb[k] = h; lb[k] = __float2bfloat16(p - __bfloat162float(h));
        }
        *reinterpret_cast<uint4*>(Eh + base + (size_t)(t + i*256) * 8) = *reinterpret_cast<const uint4*>(hb);
        *reinterpret_cast<uint4*>(El + base + (size_t)(t + i*256) * 8) = *reinterpret_cast<const uint4*>(lb);
    }
}

// ---------------- launch ----------------
extern "C" void kernel_launch(void* const* d_in, const int* in_sizes, int n_in,
                              void* d_out, int out_size)
{
    const float* x  = (const float*)d_in[0];
    const float* y  = (const float*)d_in[1];
    const float* Wq = (const float*)d_in[2];
    const float* Wk = (const float*)d_in[3];
    const float* Wv = (const float*)d_in[4];
    const float* Wo = (const float*)d_in[5];
    const float* bo = (const float*)d_in[6];
    float* out = (float*)d_out;

    bf16 *xh,*xl,*yh,*yl,*qwh,*qwl,*kwh,*kwl,*vwh,*vwl,*owh,*owl;
    bf16 *Qh,*Ql,*Kh,*Kl,*Vnh,*Vnl,*Vth,*Vtl,*Eh,*El,*Oh,*Ol;
    cudaGetSymbolAddress((void**)&xh, g_xhi);  cudaGetSymbolAddress((void**)&xl, g_xlo);
    cudaGetSymbolAddress((void**)&yh, g_yhi);  cudaGetSymbolAddress((void**)&yl, g_ylo);
    cudaGetSymbolAddress((void**)&qwh, g_Wqhi); cudaGetSymbolAddress((void**)&qwl, g_Wqlo);
    cudaGetSymbolAddress((void**)&kwh, g_Wkhi); cudaGetSymbolAddress((void**)&kwl, g_Wklo);
    cudaGetSymbolAddress((void**)&vwh, g_Wvhi); cudaGetSymbolAddress((void**)&vwl, g_Wvlo);
    cudaGetSymbolAddress((void**)&owh, g_Wohi); cudaGetSymbolAddress((void**)&owl, g_Wolo);
    cudaGetSymbolAddress((void**)&Qh, g_Qhi);  cudaGetSymbolAddress((void**)&Ql, g_Qlo);
    cudaGetSymbolAddress((void**)&Kh, g_Khi);  cudaGetSymbolAddress((void**)&Kl, g_Klo);
    cudaGetSymbolAddress((void**)&Vnh, g_Vnhi); cudaGetSymbolAddress((void**)&Vnl, g_Vnlo);
    cudaGetSymbolAddress((void**)&Vth, g_Vthi); cudaGetSymbolAddress((void**)&Vtl, g_Vtlo);
    cudaGetSymbolAddress((void**)&Eh, g_Ehi);  cudaGetSymbolAddress((void**)&El, g_Elo);
    cudaGetSymbolAddress((void**)&Oh, g_Ohi);  cudaGetSymbolAddress((void**)&Ol, g_Olo);
    cudaFuncSetAttribute(gemm3<0>, cudaFuncAttributeMaxDynamicSharedMemorySize, GSMEM);
    cudaFuncSetAttribute(gemm3<2>, cudaFuncAttributeMaxDynamicSharedMemorySize, GSMEM);

    // input splits
    split_f32<<<MQ*EMBED/1024, 256>>>(x, xh, xl, MQ*EMBED);
    split_f32<<<MK*EMBED/1024, 256>>>(y, yh, yl, MK*EMBED);
    split_f32<<<EMBED*EMBED/1024, 256>>>(Wq, qwh, qwl, EMBED*EMBED);
    split_f32<<<EMBED*EMBED/1024, 256>>>(Wk, kwh, kwl, EMBED*EMBED);
    split_f32<<<EMBED*EMBED/1024, 256>>>(Wv, vwh, vwl, EMBED*EMBED);
    split_f32<<<EMBED*EMBED/1024, 256>>>(Wo, owh, owl, EMBED*EMBED);

    // Q = x @ Wq^T
    gemm3<0><<<dim3(EMBED/128, MQ/128, 1), 256, GSMEM>>>(
        xh, xl, 0, EMBED, qwh, qwl, 0, EMBED, EMBED,
        Qh, Ql, 0, EMBED, nullptr, nullptr, nullptr);
    // K = y @ Wk^T
    gemm3<0><<<dim3(EMBED/128, MK/128, 1), 256, GSMEM>>>(
        yh, yl, 0, EMBED, kwh, kwl, 0, EMBED, EMBED,
        Kh, Kl, 0, EMBED, nullptr, nullptr, nullptr);
    // V = y @ Wv^T  (normal layout)
    gemm3<0><<<dim3(EMBED/128, MK/128, 1), 256, GSMEM>>>(
        yh, yl, 0, EMBED, vwh, vwl, 0, EMBED, EMBED,
        Vnh, Vnl, 0, EMBED, nullptr, nullptr, nullptr);
    // Vt[b][d][kk]
    transposeV<<<dim3(KLEN/32, EMBED/32, NBATCH), 256>>>(Vnh, Vnl, Vth, Vtl);
    // E_b = Q_b @ K_b^T
    gemm3<0><<<dim3(KLEN/128, QLEN/128, NBATCH), 256, GSMEM>>>(
        Qh, Ql, (long long)QLEN*EMBED, EMBED,
        Kh, Kl, (long long)KLEN*EMBED, EMBED, EMBED,
        Eh, El, (long long)QLEN*KLEN, KLEN, nullptr, nullptr, nullptr);
    // softmax rows in place
    softmax_split<<<MQ, 256>>>(Eh, El);
    // O_b = P_b @ Vt_b^T
    gemm3<0><<<dim3(EMBED/128, QLEN/128, NBATCH), 256, GSMEM>>>(
        Eh, El, (long long)QLEN*KLEN, KLEN,
        Vth, Vtl, (long long)EMBED*KLEN, KLEN, KLEN,
        Oh, Ol, (long long)QLEN*EMBED, EMBED, nullptr, nullptr, nullptr);
    // out = x + O @ Wo^T + bo
    gemm3<2><<<dim3(EMBED/128, MQ/128, 1), 256, GSMEM>>>(
        Oh, Ol, 0, EMBED, owh, owl, 0, EMBED, EMBED,
        nullptr, nullptr, 0, EMBED, out, x, bo);
}

// round 5
// speedup vs baseline: 5.6282x; 2.2878x over previous
#include <cuda_runtime.h>
#include <cuda_fp16.h>
#include <stdint.h>
#include <math.h>

#define EMBED 512
#define NBATCH 8
#define QLEN 2048
#define KLEN 4096
#define MQ (NBATCH*QLEN)
#define MK (NBATCH*KLEN)

// ---------------- device scratch ----------------
__device__ __half g_x16[MQ*EMBED];
__device__ __half g_y16[MK*EMBED];
__device__ __half g_Wq16[EMBED*EMBED], g_Wk16[EMBED*EMBED], g_Wv16[EMBED*EMBED], g_Wo16[EMBED*EMBED];
__device__ __half g_Q16[MQ*EMBED];
__device__ __half g_K16[MK*EMBED];
__device__ __half g_Vn16[MK*EMBED];
__device__ __half g_Vt16[(size_t)NBATCH*EMBED*KLEN];
__device__ __half g_E16[(size_t)MQ*KLEN];
__device__ __half g_O16[MQ*EMBED];

// ---------------- helpers ----------------
__device__ __forceinline__ uint32_t smem_u32(const void* p){
    uint32_t a;
    asm("{ .reg .u64 t; cvta.to.shared.u64 t, %1; cvt.u32.u64 %0, t; }" : "=r"(a) : "l"(p));
    return a;
}
#define CP16(s,g)   asm volatile("cp.async.cg.shared.global [%0], [%1], 16;" :: "r"(s), "l"(g) : "memory")
#define CP_COMMIT() asm volatile("cp.async.commit_group;" ::: "memory")
#define CP_WAIT1()  asm volatile("cp.async.wait_group 1;" ::: "memory")
#define CP_WAIT0()  asm volatile("cp.async.wait_group 0;" ::: "memory")

__device__ __forceinline__ void ldm4(uint32_t* r, uint32_t a){
    asm volatile("ldmatrix.sync.aligned.m8n8.x4.shared.b16 {%0,%1,%2,%3}, [%4];"
        : "=r"(r[0]), "=r"(r[1]), "=r"(r[2]), "=r"(r[3]) : "r"(a));
}
__device__ __forceinline__ void mma_f16(float* c, const uint32_t* a, const uint32_t* b){
    asm volatile("mma.sync.aligned.m16n8k16.row.col.f32.f16.f16.f32 "
        "{%0,%1,%2,%3}, {%4,%5,%6,%7}, {%8,%9}, {%0,%1,%2,%3};"
        : "+f"(c[0]), "+f"(c[1]), "+f"(c[2]), "+f"(c[3])
        : "r"(a[0]), "r"(a[1]), "r"(a[2]), "r"(a[3]), "r"(b[0]), "r"(b[1]));
}

// ---------------- single-term fp16 mma.sync GEMM ----------------
// D[m][n] = sum_k A[m][k]*B[n][k]. Tile 128x128, K-stage 64 (2 sub-chunks of 32),
// double-buffered cp.async. 256 thr = 8 warps (4 over m x 2 over n; warp 32m x 64n).
// EPI 0: fp16 out. EPI 1: f32 out = acc + resid + bias.
#define GSMEM (2*32768 + 1024)

template<int EPI>
__global__ void __launch_bounds__(256, 1)
gemm1(const __half* __restrict__ A, long long sA, int lda,
      const __half* __restrict__ B, long long sB, int ldb,
      int Kdim,
      __half* __restrict__ C16, long long sC, int ldc,
      float* __restrict__ Cf, const float* __restrict__ resid, const float* __restrict__ bias)
{
    extern __shared__ char dynsm[];
    const uint32_t tiles = (smem_u32(dynsm) + 1023u) & ~1023u;
    const int tid = threadIdx.x, lane = tid & 31, wid = tid >> 5;
    const int wm = wid & 3, wn = wid >> 2;
    const int m0 = blockIdx.y * 128, n0 = blockIdx.x * 128, b = blockIdx.z;
    A += (size_t)b * sA;  B += (size_t)b * sB;
    if (EPI == 0) C16 += (size_t)b * sC;

    float acc[2][8][4];
    #pragma unroll
    for (int i = 0; i < 2; i++)
        #pragma unroll
        for (int j = 0; j < 8; j++)
            #pragma unroll
            for (int k = 0; k < 4; k++) acc[i][j][k] = 0.f;

    // ldmatrix lane addressing (64B rows, 16B chunks, swizzle: ch ^= (row>>1)&3)
    const int r_lane = (lane & 7) + ((lane >> 3) & 1) * 8;
    uint32_t aRow[2], aSw[2];
    #pragma unroll
    for (int mt = 0; mt < 2; mt++){
        int m_loc = wm * 32 + mt * 16 + r_lane;
        aRow[mt] = (uint32_t)(m_loc * 64);
        aSw[mt]  = (uint32_t)((m_loc >> 1) & 3);
    }
    const uint32_t aCk = (lane >> 4) & 1;
    uint32_t bRow[4], bSw[4];
    {
        int n_base = wn * 64 + ((lane >> 4) & 1) * 8 + (lane & 7);
        #pragma unroll
        for (int g = 0; g < 4; g++){
            int n_loc = n_base + g * 16;
            bRow[g] = (uint32_t)(n_loc * 64);
            bSw[g]  = (uint32_t)((n_loc >> 1) & 3);
        }
    }
    const uint32_t bCk = (lane >> 3) & 1;

    const int C = Kdim >> 6;    // 64-wide K stages (all Kdims are multiples of 64)

    auto load_stage = [&](int c){
        const uint32_t sb = tiles + (c & 1) * 32768;
        const int k0 = c << 6;
        #pragma unroll
        for (int sc = 0; sc < 2; sc++){
            #pragma unroll
            for (int half = 0; half < 2; half++){
                int row = (tid >> 2) + half * 64;
                int ch  = tid & 3;
                uint32_t so = (uint32_t)(row * 64 + ((ch ^ ((row >> 1) & 3)) << 4));
                size_t ga = (size_t)(m0 + row) * lda + k0 + sc * 32 + ch * 8;
                size_t gb = (size_t)(n0 + row) * ldb + k0 + sc * 32 + ch * 8;
                CP16(sb +         sc * 8192 + so, A + ga);
                CP16(sb + 16384 + sc * 8192 + so, B + gb);
            }
        }
    };

    load_stage(0); CP_COMMIT();

    for (int c = 0; c < C; c++){
        if (c + 1 < C){ load_stage(c + 1); CP_COMMIT(); CP_WAIT1(); }
        else          { CP_WAIT0(); }
        __syncthreads();

        const uint32_t sb = tiles + (c & 1) * 32768;
        #pragma unroll
        for (int sc = 0; sc < 2; sc++){
            const uint32_t sa_b = sb + sc * 8192;
            const uint32_t sb_b = sb + 16384 + sc * 8192;
            #pragma unroll
            for (int ks = 0; ks < 2; ks++){
                uint32_t ah[2][4];
                #pragma unroll
                for (int mt = 0; mt < 2; mt++){
                    uint32_t off = aRow[mt] + ((((uint32_t)(2 * ks) + aCk) ^ aSw[mt]) << 4);
                    ldm4(ah[mt], sa_b + off);
                }
                uint32_t bb[8][2];
                #pragma unroll
                for (int g = 0; g < 4; g++){
                    uint32_t off = bRow[g] + ((((uint32_t)(2 * ks) + bCk) ^ bSw[g]) << 4);
                    uint32_t q[4];
                    ldm4(q, sb_b + off);
                    bb[2*g][0]=q[0]; bb[2*g][1]=q[1]; bb[2*g+1][0]=q[2]; bb[2*g+1][1]=q[3];
                }
                #pragma unroll
                for (int mt = 0; mt < 2; mt++)
                    #pragma unroll
                    for (int nf = 0; nf < 8; nf++)
                        mma_f16(acc[mt][nf], ah[mt], bb[nf]);
            }
        }
        __syncthreads();
    }

    // ---------------- epilogue ----------------
    const int er = lane >> 2, ec = (lane & 3) * 2;
    #pragma unroll
    for (int mt = 0; mt < 2; mt++)
        #pragma unroll
        for (int nf = 0; nf < 8; nf++){
            const int n = n0 + wn * 64 + nf * 8 + ec;
            #pragma unroll
            for (int rr = 0; rr < 2; rr++){
                const int m = m0 + wm * 32 + mt * 16 + er + rr * 8;
                float v0 = acc[mt][nf][rr * 2], v1 = acc[mt][nf][rr * 2 + 1];
                if (EPI == 0){
                    __half2 hp = __floats2half2_rn(v0, v1);
                    *reinterpret_cast<uint32_t*>(C16 + (size_t)m * ldc + n) = *reinterpret_cast<uint32_t*>(&hp);
                } else {
                    size_t off = (size_t)m * ldc + n;
                    float2 rv = *reinterpret_cast<const float2*>(resid + off);
                    float2 bv = *reinterpret_cast<const float2*>(bias + n);
                    float2 o; o.x = v0 + rv.x + bv.x; o.y = v1 + rv.y + bv.y;
                    *reinterpret_cast<float2*>(Cf + off) = o;
                }
            }
        }
}

// ---------------- f32 -> fp16 convert ----------------
__global__ void __launch_bounds__(256, 1)
cvt16(const float* __restrict__ in, __half* __restrict__ out, int n)
{
    int i = (blockIdx.x * 256 + threadIdx.x) * 4;
    if (i >= n) return;
    float4 v = *reinterpret_cast<const float4*>(in + i);
    __half2 a = __floats2half2_rn(v.x, v.y);
    __half2 b = __floats2half2_rn(v.z, v.w);
    uint2 o;
    o.x = *reinterpret_cast<uint32_t*>(&a);
    o.y = *reinterpret_cast<uint32_t*>(&b);
    *reinterpret_cast<uint2*>(out + i) = o;
}

// ---------------- V transpose: [b][kk][d] -> [b][d][kk] (fp16) ----------------
__global__ void __launch_bounds__(256, 1)
transpose16(const __half* __restrict__ Vn, __half* __restrict__ Vt)
{
    __shared__ __half s[32][33];
    const int b = blockIdx.z, kk0 = blockIdx.x * 32, d0 = blockIdx.y * 32;
    const int tx = threadIdx.x & 31, ty = threadIdx.x >> 5;
    const __half* src = Vn + (size_t)b * KLEN * EMBED;
    #pragma unroll
    for (int i = ty; i < 32; i += 8)
        s[i][tx] = src[(size_t)(kk0 + i) * EMBED + d0 + tx];
    __syncthreads();
    __half* dst = Vt + (size_t)b * EMBED * KLEN;
    #pragma unroll
    for (int i = ty; i < 32; i += 8)
        dst[(size_t)(d0 + i) * KLEN + kk0 + tx] = s[tx][i];
}

// ---------------- fp16 row softmax (in place), scale 1/sqrt(512) ----------------
__inline__ __device__ float wmax(float v){
    #pragma unroll
    for (int o = 16; o; o >>= 1) v = fmaxf(v, __shfl_xor_sync(0xffffffffu, v, o));
    return v;
}
__inline__ __device__ float wsum(float v){
    #pragma unroll
    for (int o = 16; o; o >>= 1) v += __shfl_xor_sync(0xffffffffu, v, o);
    return v;
}
__global__ void __launch_bounds__(256, 1)
softmax16(__half* __restrict__ E)
{
    const size_t base = (size_t)blockIdx.x * KLEN;
    const int t = threadIdx.x;
    const float scale = rsqrtf((float)EMBED);
    __shared__ float red[8];

    float v[16];
    #pragma unroll
    for (int i = 0; i < 2; i++){
        uint4 u = *reinterpret_cast<const uint4*>(E + base + (size_t)(t + i*256) * 8);
        const __half* hp = reinterpret_cast<const __half*>(&u);
        #pragma unroll
        for (int k = 0; k < 8; k++) v[i*8+k] = __half2float(hp[k]) * scale;
    }
    float mx = -INFINITY;
    #pragma unroll
    for (int i = 0; i < 16; i++) mx = fmaxf(mx, v[i]);
    mx = wmax(mx);
    if ((t & 31) == 0) red[t >> 5] = mx;
    __syncthreads();
    if (t < 32){ float m = (t < 8) ? red[t] : -INFINITY; m = wmax(m); if (!t) red[0] = m; }
    __syncthreads();
    mx = red[0];
    __syncthreads();
    float sum = 0.f;
    #pragma unroll
    for (int i = 0; i < 16; i++){ v[i] = __expf(v[i] - mx); sum += v[i]; }
    sum = wsum(sum);
    if ((t & 31) == 0) red[t >> 5] = sum;
    __syncthreads();
    if (t < 32){ float s = (t < 8) ? red[t] : 0.f; s = wsum(s); if (!t) red[0] = s; }
    __syncthreads();
    const float inv = 1.f / red[0];
    #pragma unroll
    for (int i = 0; i < 2; i++){
        __align__(16) __half hb[8];
        #pragma unroll
        for (int k = 0; k < 8; k++) hb[k] = __float2half(v[i*8+k] * inv);
        *reinterpret_cast<uint4*>(E + base + (size_t)(t + i*256) * 8) = *reinterpret_cast<const uint4*>(hb);
    }
}

// ---------------- launch ----------------
extern "C" void kernel_launch(void* const* d_in, const int* in_sizes, int n_in,
                              void* d_out, int out_size)
{
    const float* x  = (const float*)d_in[0];
    const float* y  = (const float*)d_in[1];
    const float* Wq = (const float*)d_in[2];
    const float* Wk = (const float*)d_in[3];
    const float* Wv = (const float*)d_in[4];
    const float* Wo = (const float*)d_in[5];
    const float* bo = (const float*)d_in[6];
    float* out = (float*)d_out;

    __half *x16,*y16,*wq16,*wk16,*wv16,*wo16,*Q16,*K16,*Vn16,*Vt16,*E16,*O16;
    cudaGetSymbolAddress((void**)&x16,  g_x16);
    cudaGetSymbolAddress((void**)&y16,  g_y16);
    cudaGetSymbolAddress((void**)&wq16, g_Wq16);
    cudaGetSymbolAddress((void**)&wk16, g_Wk16);
    cudaGetSymbolAddress((void**)&wv16, g_Wv16);
    cudaGetSymbolAddress((void**)&wo16, g_Wo16);
    cudaGetSymbolAddress((void**)&Q16,  g_Q16);
    cudaGetSymbolAddress((void**)&K16,  g_K16);
    cudaGetSymbolAddress((void**)&Vn16, g_Vn16);
    cudaGetSymbolAddress((void**)&Vt16, g_Vt16);
    cudaGetSymbolAddress((void**)&E16,  g_E16);
    cudaGetSymbolAddress((void**)&O16,  g_O16);
    cudaFuncSetAttribute(gemm1<0>, cudaFuncAttributeMaxDynamicSharedMemorySize, GSMEM);
    cudaFuncSetAttribute(gemm1<1>, cudaFuncAttributeMaxDynamicSharedMemorySize, GSMEM);

    // converts
    cvt16<<<MQ*EMBED/1024, 256>>>(x, x16, MQ*EMBED);
    cvt16<<<MK*EMBED/1024, 256>>>(y, y16, MK*EMBED);
    cvt16<<<EMBED*EMBED/1024, 256>>>(Wq, wq16, EMBED*EMBED);
    cvt16<<<EMBED*EMBED/1024, 256>>>(Wk, wk16, EMBED*EMBED);
    cvt16<<<EMBED*EMBED/1024, 256>>>(Wv, wv16, EMBED*EMBED);
    cvt16<<<EMBED*EMBED/1024, 256>>>(Wo, wo16, EMBED*EMBED);

    // Q = x @ Wq^T
    gemm1<0><<<dim3(EMBED/128, MQ/128, 1), 256, GSMEM>>>(
        x16, 0, EMBED, wq16, 0, EMBED, EMBED, Q16, 0, EMBED, nullptr, nullptr, nullptr);
    // K = y @ Wk^T
    gemm1<0><<<dim3(EMBED/128, MK/128, 1), 256, GSMEM>>>(
        y16, 0, EMBED, wk16, 0, EMBED, EMBED, K16, 0, EMBED, nullptr, nullptr, nullptr);
    // V = y @ Wv^T
    gemm1<0><<<dim3(EMBED/128, MK/128, 1), 256, GSMEM>>>(
        y16, 0, EMBED, wv16, 0, EMBED, EMBED, Vn16, 0, EMBED, nullptr, nullptr, nullptr);
    // Vt[b][d][kk]
    transpose16<<<dim3(KLEN/32, EMBED/32, NBATCH), 256>>>(Vn16, Vt16);
    // E_b = Q_b @ K_b^T
    gemm1<0><<<dim3(KLEN/128, QLEN/128, NBATCH), 256, GSMEM>>>(
        Q16, (long long)QLEN*EMBED, EMBED,
        K16, (long long)KLEN*EMBED, EMBED, EMBED,
        E16, (long long)QLEN*KLEN, KLEN, nullptr, nullptr, nullptr);
    // softmax rows in place
    softmax16<<<MQ, 256>>>(E16);
    // O_b = P_b @ Vt_b^T
    gemm1<0><<<dim3(EMBED/128, QLEN/128, NBATCH), 256, GSMEM>>>(
        E16, (long long)QLEN*KLEN, KLEN,
        Vt16, (long long)EMBED*KLEN, KLEN, KLEN,
        O16, (long long)QLEN*EMBED, EMBED, nullptr, nullptr, nullptr);
    // out = x + O @ Wo^T + bo
    gemm1<1><<<dim3(EMBED/128, MQ/128, 1), 256, GSMEM>>>(
        O16, 0, EMBED, wo16, 0, EMBED, EMBED,
        nullptr, 0, EMBED, out, x, bo);
}

// round 6
// speedup vs baseline: 6.3862x; 1.1347x over previous
#include <cuda_runtime.h>
#include <cuda_fp16.h>
#include <stdint.h>
#include <math.h>

#define EMBED 512
#define NBATCH 8
#define QLEN 2048
#define KLEN 4096
#define MQ (NBATCH*QLEN)
#define MK (NBATCH*KLEN)

__device__ __half g_x16[MQ*EMBED];
__device__ __half g_y16[MK*EMBED];
__device__ __half g_W16[4][EMBED*EMBED];     // q,k,v,o
__device__ __half g_Q16[MQ*EMBED];
__device__ __half g_K16[MK*EMBED];
__device__ __half g_Vt16[(size_t)NBATCH*EMBED*KLEN];
__device__ __half g_E16[(size_t)MQ*KLEN];
__device__ __half g_O16[MQ*EMBED];

__device__ __forceinline__ uint32_t smem_u32(const void* p){
    uint32_t a;
    asm("{ .reg .u64 t; cvta.to.shared.u64 t, %1; cvt.u32.u64 %0, t; }" : "=r"(a) : "l"(p));
    return a;
}
#define CP16(s,g)   asm volatile("cp.async.cg.shared.global [%0], [%1], 16;" :: "r"(s), "l"(g) : "memory")
#define CP_COMMIT() asm volatile("cp.async.commit_group;" ::: "memory")
#define CP_WAIT3()  asm volatile("cp.async.wait_group 3;" ::: "memory")
#define CP_WAIT2()  asm volatile("cp.async.wait_group 2;" ::: "memory")
#define CP_WAIT1()  asm volatile("cp.async.wait_group 1;" ::: "memory")
#define CP_WAIT0()  asm volatile("cp.async.wait_group 0;" ::: "memory")

__device__ __forceinline__ void ldm4(uint32_t* r, uint32_t a){
    asm volatile("ldmatrix.sync.aligned.m8n8.x4.shared.b16 {%0,%1,%2,%3}, [%4];"
        : "=r"(r[0]), "=r"(r[1]), "=r"(r[2]), "=r"(r[3]) : "r"(a));
}
__device__ __forceinline__ void mma_f16(float* c, const uint32_t* a, const uint32_t* b){
    asm volatile("mma.sync.aligned.m16n8k16.row.col.f32.f16.f16.f32 "
        "{%0,%1,%2,%3}, {%4,%5,%6,%7}, {%8,%9}, {%0,%1,%2,%3};"
        : "+f"(c[0]), "+f"(c[1]), "+f"(c[2]), "+f"(c[3])
        : "r"(a[0]), "r"(a[1]), "r"(a[2]), "r"(a[3]), "r"(b[0]), "r"(b[1]));
}

// ---------------- fp16 mma.sync GEMM, tile 128x256x32, 4-stage pipeline ----------------
// D[m][n] = sum_k A[m][k]*B[n][k].  8 warps = 2(m) x 4(n); warp tile 64x64.
// EPI 0: fp16 out (scaled).  EPI 1: V-transpose epilogue -> Vt[b][d][kk].
// EPI 2: f32 out = acc + resid + bias.
#define STAGE_B 24576                    // A 8KB + B 16KB
#define GSMEM   (4*STAGE_B + 1024)      // also covers EPI1 staging (256*136*2 B)

template<int EPI>
__global__ void __launch_bounds__(256, 1)
gemm2(const __half* __restrict__ A, long long sA, int lda,
      const __half* __restrict__ B, long long sB, int ldb,
      int Kdim,
      __half* __restrict__ C16, long long sC, int ldc,
      float* __restrict__ Cf, const float* __restrict__ resid,
      const float* __restrict__ bias, float scale)
{
    extern __shared__ char dynsm[];
    const uint32_t smbase = smem_u32(dynsm);
    const uint32_t tiles = (smbase + 1023u) & ~1023u;
    const int tid = threadIdx.x, lane = tid & 31, wid = tid >> 5;
    const int wm = wid & 1, wn = wid >> 1;
    const int m0 = blockIdx.y * 128, n0 = blockIdx.x * 256, b = blockIdx.z;
    A += (size_t)b * sA;  B += (size_t)b * sB;
    if (EPI == 0) C16 += (size_t)b * sC;

    float acc[4][8][4];
    #pragma unroll
    for (int i = 0; i < 4; i++)
        #pragma unroll
        for (int j = 0; j < 8; j++)
            #pragma unroll
            for (int k = 0; k < 4; k++) acc[i][j][k] = 0.f;

    // ldmatrix addressing (rows of 64B = 4x16B chunks, swizzle ch ^= (row>>1)&3)
    const int r_lane = (lane & 7) + ((lane >> 3) & 1) * 8;
    uint32_t aRow[4], aSw[4];
    #pragma unroll
    for (int mt = 0; mt < 4; mt++){
        int m_loc = wm * 64 + mt * 16 + r_lane;
        aRow[mt] = (uint32_t)(m_loc * 64);
        aSw[mt]  = (uint32_t)((m_loc >> 1) & 3);
    }
    const uint32_t aCk = (lane >> 4) & 1;
    uint32_t bRow[4], bSw[4];
    {
        int n_base = wn * 64 + ((lane >> 4) & 1) * 8 + (lane & 7);
        #pragma unroll
        for (int g = 0; g < 4; g++){
            int n_loc = n_base + g * 16;
            bRow[g] = (uint32_t)(n_loc * 64);
            bSw[g]  = (uint32_t)((n_loc >> 1) & 3);
        }
    }
    const uint32_t bCk = (lane >> 3) & 1;

    const int C = Kdim >> 5;

    auto load_stage = [&](int c){
        const uint32_t sb = tiles + (c & 3) * STAGE_B;
        const int k0 = c << 5;
        #pragma unroll
        for (int i = 0; i < 2; i++){           // A: 128 rows x 4 chunks
            int idx = tid + i * 256;
            int row = idx >> 2, ch = idx & 3;
            uint32_t so = (uint32_t)(row * 64 + ((ch ^ ((row >> 1) & 3)) << 4));
            CP16(sb + so, A + (size_t)(m0 + row) * lda + k0 + ch * 8);
        }
        #pragma unroll
        for (int i = 0; i < 4; i++){           // B: 256 rows x 4 chunks
            int idx = tid + i * 256;
            int row = idx >> 2, ch = idx & 3;
            uint32_t so = (uint32_t)(row * 64 + ((ch ^ ((row >> 1) & 3)) << 4));
            CP16(sb + 8192 + so, B + (size_t)(n0 + row) * ldb + k0 + ch * 8);
        }
    };

    load_stage(0); CP_COMMIT();
    load_stage(1); CP_COMMIT();
    load_stage(2); CP_COMMIT();

    for (int c = 0; c < C; c++){
        if (c + 3 < C){ load_stage(c + 3); CP_COMMIT(); }
        const int lag = C - 1 - c;
        if      (lag >= 3) CP_WAIT3();
        else if (lag == 2) CP_WAIT2();
        else if (lag == 1) CP_WAIT1();
        else               CP_WAIT0();
        __syncthreads();

        const uint32_t sb = tiles + (c & 3) * STAGE_B;
        #pragma unroll
        for (int ks = 0; ks < 2; ks++){
            uint32_t ah[4][4];
            #pragma unroll
            for (int mt = 0; mt < 4; mt++){
                uint32_t off = aRow[mt] + ((((uint32_t)(2 * ks) + aCk) ^ aSw[mt]) << 4);
                ldm4(ah[mt], sb + off);
            }
            uint32_t bb[8][2];
            #pragma unroll
            for (int g = 0; g < 4; g++){
                uint32_t off = bRow[g] + ((((uint32_t)(2 * ks) + bCk) ^ bSw[g]) << 4);
                uint32_t q[4];
                ldm4(q, sb + 8192 + off);
                bb[2*g][0]=q[0]; bb[2*g][1]=q[1]; bb[2*g+1][0]=q[2]; bb[2*g+1][1]=q[3];
            }
            #pragma unroll
            for (int mt = 0; mt < 4; mt++)
                #pragma unroll
                for (int nf = 0; nf < 8; nf++)
                    mma_f16(acc[mt][nf], ah[mt], bb[nf]);
        }
        __syncthreads();
    }

    // ---------------- epilogue ----------------
    const int er = lane >> 2, ec = (lane & 3) * 2;
    if (EPI == 1){
        // stage transposed tile in smem: s[d_local][kk_local], stride 136
        __half* s = reinterpret_cast<__half*>(dynsm + (tiles - smbase));
        __syncthreads();
        #pragma unroll
        for (int mt = 0; mt < 4; mt++)
            #pragma unroll
            for (int nf = 0; nf < 8; nf++){
                const int dn = wn * 64 + nf * 8 + ec;
                #pragma unroll
                for (int rr = 0; rr < 2; rr++){
                    const int km = wm * 64 + mt * 16 + er + rr * 8;
                    s[(size_t)dn * 136 + km]       = __float2half(acc[mt][nf][rr*2]);
                    s[(size_t)(dn+1) * 136 + km]   = __float2half(acc[mt][nf][rr*2+1]);
                }
            }
        __syncthreads();
        const int batch = m0 / KLEN;
        const int kkb   = m0 % KLEN;
        #pragma unroll
        for (int pass = 0; pass < 16; pass++){
            int drow = (tid >> 4) + pass * 16;          // 0..255
            int seg  = tid & 15;                         // 16 x 8 halfs = 128
            uint4 v = *reinterpret_cast<const uint4*>(s + (size_t)drow * 136 + seg * 8);
            *reinterpret_cast<uint4*>(C16 + ((size_t)batch * EMBED + n0 + drow) * KLEN + kkb + seg * 8) = v;
        }
        return;
    }
    #pragma unroll
    for (int mt = 0; mt < 4; mt++)
        #pragma unroll
        for (int nf = 0; nf < 8; nf++){
            const int n = n0 + wn * 64 + nf * 8 + ec;
            #pragma unroll
            for (int rr = 0; rr < 2; rr++){
                const int m = m0 + wm * 64 + mt * 16 + er + rr * 8;
                float v0 = acc[mt][nf][rr * 2] * scale, v1 = acc[mt][nf][rr * 2 + 1] * scale;
                if (EPI == 0){
                    __half2 hp = __floats2half2_rn(v0, v1);
                    *reinterpret_cast<uint32_t*>(C16 + (size_t)m * ldc + n) = *reinterpret_cast<uint32_t*>(&hp);
                } else {
                    size_t off = (size_t)m * ldc + n;
                    float2 rv = *reinterpret_cast<const float2*>(resid + off);
                    float2 bv = *reinterpret_cast<const float2*>(bias + n);
                    float2 o; o.x = v0 + rv.x + bv.x; o.y = v1 + rv.y + bv.y;
                    *reinterpret_cast<float2*>(Cf + off) = o;
                }
            }
        }
}

// ---------------- converts ----------------
__global__ void __launch_bounds__(256, 1)
cvt16(const float* __restrict__ in, __half* __restrict__ out, int n)
{
    int i = (blockIdx.x * 256 + threadIdx.x) * 4;
    if (i >= n) return;
    float4 v = *reinterpret_cast<const float4*>(in + i);
    __half2 a = __floats2half2_rn(v.x, v.y);
    __half2 b = __floats2half2_rn(v.z, v.w);
    uint2 o;
    o.x = *reinterpret_cast<uint32_t*>(&a);
    o.y = *reinterpret_cast<uint32_t*>(&b);
    *reinterpret_cast<uint2*>(out + i) = o;
}
__global__ void __launch_bounds__(256, 1)
cvtW(const float* __restrict__ w0, const float* __restrict__ w1,
     const float* __restrict__ w2, const float* __restrict__ w3,
     __half* __restrict__ out)
{
    const float* src = (blockIdx.y == 0) ? w0 : (blockIdx.y == 1) ? w1 : (blockIdx.y == 2) ? w2 : w3;
    __half* dst = out + (size_t)blockIdx.y * EMBED * EMBED;
    int i = (blockIdx.x * 256 + threadIdx.x) * 4;
    float4 v = *reinterpret_cast<const float4*>(src + i);
    __half2 a = __floats2half2_rn(v.x, v.y);
    __half2 b = __floats2half2_rn(v.z, v.w);
    uint2 o;
    o.x = *reinterpret_cast<uint32_t*>(&a);
    o.y = *reinterpret_cast<uint32_t*>(&b);
    *reinterpret_cast<uint2*>(dst + i) = o;
}

// ---------------- fp16 row softmax (scale pre-applied in QK epilogue) ----------------
__inline__ __device__ float wmax(float v){
    #pragma unroll
    for (int o = 16; o; o >>= 1) v = fmaxf(v, __shfl_xor_sync(0xffffffffu, v, o));
    return v;
}
__inline__ __device__ float wsum(float v){
    #pragma unroll
    for (int o = 16; o; o >>= 1) v += __shfl_xor_sync(0xffffffffu, v, o);
    return v;
}
__global__ void __launch_bounds__(256, 1)
softmax16(__half* __restrict__ E)
{
    const size_t base = (size_t)blockIdx.x * KLEN;
    const int t = threadIdx.x;
    __shared__ float red[8];

    float v[16];
    #pragma unroll
    for (int i = 0; i < 2; i++){
        uint4 u = *reinterpret_cast<const uint4*>(E + base + (size_t)(t + i*256) * 8);
        const __half* hp = reinterpret_cast<const __half*>(&u);
        #pragma unroll
        for (int k = 0; k < 8; k++) v[i*8+k] = __half2float(hp[k]);
    }
    float mx = -INFINITY;
    #pragma unroll
    for (int i = 0; i < 16; i++) mx = fmaxf(mx, v[i]);
    mx = wmax(mx);
    if ((t & 31) == 0) red[t >> 5] = mx;
    __syncthreads();
    if (t < 32){ float m = (t < 8) ? red[t] : -INFINITY; m = wmax(m); if (!t) red[0] = m; }
    __syncthreads();
    mx = red[0];
    __syncthreads();
    float sum = 0.f;
    #pragma unroll
    for (int i = 0; i < 16; i++){ v[i] = __expf(v[i] - mx); sum += v[i]; }
    sum = wsum(sum);
    if ((t & 31) == 0) red[t >> 5] = sum;
    __syncthreads();
    if (t < 32){ float s = (t < 8) ? red[t] : 0.f; s = wsum(s); if (!t) red[0] = s; }
    __syncthreads();
    const float inv = 1.f / red[0];
    #pragma unroll
    for (int i = 0; i < 2; i++){
        __align__(16) __half hb[8];
        #pragma unroll
        for (int k = 0; k < 8; k++) hb[k] = __float2half(v[i*8+k] * inv);
        *reinterpret_cast<uint4*>(E + base + (size_t)(t + i*256) * 8) = *reinterpret_cast<const uint4*>(hb);
    }
}

// ---------------- launch ----------------
extern "C" void kernel_launch(void* const* d_in, const int* in_sizes, int n_in,
                              void* d_out, int out_size)
{
    const float* x  = (const float*)d_in[0];
    const float* y  = (const float*)d_in[1];
    const float* Wq = (const float*)d_in[2];
    const float* Wk = (const float*)d_in[3];
    const float* Wv = (const float*)d_in[4];
    const float* Wo = (const float*)d_in[5];
    const float* bo = (const float*)d_in[6];
    float* out = (float*)d_out;

    __half *x16,*y16,*W16,*Q16,*K16,*Vt16,*E16,*O16;
    cudaGetSymbolAddress((void**)&x16,  g_x16);
    cudaGetSymbolAddress((void**)&y16,  g_y16);
    cudaGetSymbolAddress((void**)&W16,  g_W16);
    cudaGetSymbolAddress((void**)&Q16,  g_Q16);
    cudaGetSymbolAddress((void**)&K16,  g_K16);
    cudaGetSymbolAddress((void**)&Vt16, g_Vt16);
    cudaGetSymbolAddress((void**)&E16,  g_E16);
    cudaGetSymbolAddress((void**)&O16,  g_O16);
    __half* wq16 = W16;
    __half* wk16 = W16 + (size_t)EMBED*EMBED;
    __half* wv16 = W16 + (size_t)2*EMBED*EMBED;
    __half* wo16 = W16 + (size_t)3*EMBED*EMBED;
    cudaFuncSetAttribute(gemm2<0>, cudaFuncAttributeMaxDynamicSharedMemorySize, GSMEM);
    cudaFuncSetAttribute(gemm2<1>, cudaFuncAttributeMaxDynamicSharedMemorySize, GSMEM);
    cudaFuncSetAttribute(gemm2<2>, cudaFuncAttributeMaxDynamicSharedMemorySize, GSMEM);

    const float sc = 1.0f / sqrtf((float)EMBED);

    cvt16<<<MQ*EMBED/1024, 256>>>(x, x16, MQ*EMBED);
    cvt16<<<MK*EMBED/1024, 256>>>(y, y16, MK*EMBED);
    cvtW<<<dim3(EMBED*EMBED/1024, 4), 256>>>(Wq, Wk, Wv, Wo, W16);

    // Q = x @ Wq^T
    gemm2<0><<<dim3(EMBED/256, MQ/128, 1), 256, GSMEM>>>(
        x16, 0, EMBED, wq16, 0, EMBED, EMBED, Q16, 0, EMBED, nullptr, nullptr, nullptr, 1.0f);
    // K = y @ Wk^T
    gemm2<0><<<dim3(EMBED/256, MK/128, 1), 256, GSMEM>>>(
        y16, 0, EMBED, wk16, 0, EMBED, EMBED, K16, 0, EMBED, nullptr, nullptr, nullptr, 1.0f);
    // V = y @ Wv^T, transposed epilogue -> Vt[b][d][kk]
    gemm2<1><<<dim3(EMBED/256, MK/128, 1), 256, GSMEM>>>(
        y16, 0, EMBED, wv16, 0, EMBED, EMBED, Vt16, 0, 0, nullptr, nullptr, nullptr, 1.0f);
    // E_b = (Q_b @ K_b^T) * sc
    gemm2<0><<<dim3(KLEN/256, QLEN/128, NBATCH), 256, GSMEM>>>(
        Q16, (long long)QLEN*EMBED, EMBED,
        K16, (long long)KLEN*EMBED, EMBED, EMBED,
        E16, (long long)QLEN*KLEN, KLEN, nullptr, nullptr, nullptr, sc);
    // softmax rows in place
    softmax16<<<MQ, 256>>>(E16);
    // O_b = P_b @ Vt_b^T
    gemm2<0><<<dim3(EMBED/256, QLEN/128, NBATCH), 256, GSMEM>>>(
        E16, (long long)QLEN*KLEN, KLEN,
        Vt16, (long long)EMBED*KLEN, KLEN, KLEN,
        O16, (long long)QLEN*EMBED, EMBED, nullptr, nullptr, nullptr, 1.0f);
    // out = x + O @ Wo^T + bo
    gemm2<2><<<dim3(EMBED/256, MQ/128, 1), 256, GSMEM>>>(
        O16, 0, EMBED, wo16, 0, EMBED, EMBED,
        nullptr, 0, EMBED, out, x, bo, 1.0f);
}

// round 7
// speedup vs baseline: 7.3136x; 1.1452x over previous
#include <cuda_runtime.h>
#include <cuda_fp16.h>
#include <stdint.h>
#include <math.h>

#define EMBED 512
#define NBATCH 8
#define QLEN 2048
#define KLEN 4096
#define MQ (NBATCH*QLEN)
#define MK (NBATCH*KLEN)

__device__ __half g_x16[MQ*EMBED];
__device__ __half g_y16[MK*EMBED];
__device__ __half g_W16[4][EMBED*EMBED];     // q,k,v,o
__device__ __half g_Q16[MQ*EMBED];
__device__ __half g_K16[MK*EMBED];
__device__ __half g_Vt16[(size_t)NBATCH*EMBED*KLEN];
__device__ __half g_E16[(size_t)MQ*KLEN];
__device__ __half g_O16[MQ*EMBED];

__device__ __forceinline__ uint32_t smem_u32(const void* p){
    uint32_t a;
    asm("{ .reg .u64 t; cvta.to.shared.u64 t, %1; cvt.u32.u64 %0, t; }" : "=r"(a) : "l"(p));
    return a;
}
#define CP16(s,g)   asm volatile("cp.async.cg.shared.global [%0], [%1], 16;" :: "r"(s), "l"(g) : "memory")
#define CP_COMMIT() asm volatile("cp.async.commit_group;" ::: "memory")
#define CP_WAIT3()  asm volatile("cp.async.wait_group 3;" ::: "memory")
#define CP_WAIT2()  asm volatile("cp.async.wait_group 2;" ::: "memory")
#define CP_WAIT1()  asm volatile("cp.async.wait_group 1;" ::: "memory")
#define CP_WAIT0()  asm volatile("cp.async.wait_group 0;" ::: "memory")

__device__ __forceinline__ void ldm4(uint32_t* r, uint32_t a){
    asm volatile("ldmatrix.sync.aligned.m8n8.x4.shared.b16 {%0,%1,%2,%3}, [%4];"
        : "=r"(r[0]), "=r"(r[1]), "=r"(r[2]), "=r"(r[3]) : "r"(a));
}
__device__ __forceinline__ void mma_f16(float* c, const uint32_t* a, const uint32_t* b){
    asm volatile("mma.sync.aligned.m16n8k16.row.col.f32.f16.f16.f32 "
        "{%0,%1,%2,%3}, {%4,%5,%6,%7}, {%8,%9}, {%0,%1,%2,%3};"
        : "+f"(c[0]), "+f"(c[1]), "+f"(c[2]), "+f"(c[3])
        : "r"(a[0]), "r"(a[1]), "r"(a[2]), "r"(a[3]), "r"(b[0]), "r"(b[1]));
}

// ---------------- fp16 mma.sync GEMM, tile 128x128x32, 4-stage, 2 CTA/SM ----------------
// D[m][n] = sum_k A[m][k]*B[n][k].  8 warps = 4(m) x 2(n); warp tile 32x64.
// EPI 0: fp16 out (scaled).  EPI 1: V-transpose epilogue -> Vt[b][d][kk].
// EPI 2: f32 out = acc + resid + bias.
#define STAGE_B 16384                 // A 8KB + B 8KB
#define GSMEM   (4*STAGE_B + 1024)

template<int EPI>
__global__ void __launch_bounds__(256, 2)
gemm2(const __half* __restrict__ A, long long sA, int lda,
      const __half* __restrict__ B, long long sB, int ldb,
      int Kdim,
      __half* __restrict__ C16, long long sC, int ldc,
      float* __restrict__ Cf, const float* __restrict__ resid,
      const float* __restrict__ bias, float scale)
{
    extern __shared__ char dynsm[];
    const uint32_t smbase = smem_u32(dynsm);
    const uint32_t tiles = (smbase + 1023u) & ~1023u;
    const int tid = threadIdx.x, lane = tid & 31, wid = tid >> 5;
    const int wm = wid & 3, wn = wid >> 2;
    const int m0 = blockIdx.y * 128, n0 = blockIdx.x * 128, b = blockIdx.z;
    A += (size_t)b * sA;  B += (size_t)b * sB;
    if (EPI == 0) C16 += (size_t)b * sC;

    float acc[2][8][4];
    #pragma unroll
    for (int i = 0; i < 2; i++)
        #pragma unroll
        for (int j = 0; j < 8; j++)
            #pragma unroll
            for (int k = 0; k < 4; k++) acc[i][j][k] = 0.f;

    // ldmatrix addressing (64B rows = 4x16B chunks, swizzle ch ^= (row>>1)&3)
    const int r_lane = (lane & 7) + ((lane >> 3) & 1) * 8;
    uint32_t aRow[2], aSw[2];
    #pragma unroll
    for (int mt = 0; mt < 2; mt++){
        int m_loc = wm * 32 + mt * 16 + r_lane;
        aRow[mt] = (uint32_t)(m_loc * 64);
        aSw[mt]  = (uint32_t)((m_loc >> 1) & 3);
    }
    const uint32_t aCk = (lane >> 4) & 1;
    uint32_t bRow[4], bSw[4];
    {
        int n_base = wn * 64 + ((lane >> 4) & 1) * 8 + (lane & 7);
        #pragma unroll
        for (int g = 0; g < 4; g++){
            int n_loc = n_base + g * 16;
            bRow[g] = (uint32_t)(n_loc * 64);
            bSw[g]  = (uint32_t)((n_loc >> 1) & 3);
        }
    }
    const uint32_t bCk = (lane >> 3) & 1;

    const int C = Kdim >> 5;

    auto load_stage = [&](int c){
        const uint32_t sb = tiles + (c & 3) * STAGE_B;
        const int k0 = c << 5;
        #pragma unroll
        for (int i = 0; i < 2; i++){           // A: 128 rows x 4 chunks
            int idx = tid + i * 256;
            int row = idx >> 2, ch = idx & 3;
            uint32_t so = (uint32_t)(row * 64 + ((ch ^ ((row >> 1) & 3)) << 4));
            CP16(sb + so, A + (size_t)(m0 + row) * lda + k0 + ch * 8);
        }
        #pragma unroll
        for (int i = 0; i < 2; i++){           // B: 128 rows x 4 chunks
            int idx = tid + i * 256;
            int row = idx >> 2, ch = idx & 3;
            uint32_t so = (uint32_t)(row * 64 + ((ch ^ ((row >> 1) & 3)) << 4));
            CP16(sb + 8192 + so, B + (size_t)(n0 + row) * ldb + k0 + ch * 8);
        }
    };

    load_stage(0); CP_COMMIT();
    load_stage(1); CP_COMMIT();
    load_stage(2); CP_COMMIT();

    for (int c = 0; c < C; c++){
        if (c + 3 < C){ load_stage(c + 3); CP_COMMIT(); }
        const int lag = C - 1 - c;
        if      (lag >= 3) CP_WAIT3();
        else if (lag == 2) CP_WAIT2();
        else if (lag == 1) CP_WAIT1();
        else               CP_WAIT0();
        __syncthreads();

        const uint32_t sb = tiles + (c & 3) * STAGE_B;
        #pragma unroll
        for (int ks = 0; ks < 2; ks++){
            uint32_t ah[2][4];
            #pragma unroll
            for (int mt = 0; mt < 2; mt++){
                uint32_t off = aRow[mt] + ((((uint32_t)(2 * ks) + aCk) ^ aSw[mt]) << 4);
                ldm4(ah[mt], sb + off);
            }
            uint32_t bb[8][2];
            #pragma unroll
            for (int g = 0; g < 4; g++){
                uint32_t off = bRow[g] + ((((uint32_t)(2 * ks) + bCk) ^ bSw[g]) << 4);
                uint32_t q[4];
                ldm4(q, sb + 8192 + off);
                bb[2*g][0]=q[0]; bb[2*g][1]=q[1]; bb[2*g+1][0]=q[2]; bb[2*g+1][1]=q[3];
            }
            #pragma unroll
            for (int mt = 0; mt < 2; mt++)
                #pragma unroll
                for (int nf = 0; nf < 8; nf++)
                    mma_f16(acc[mt][nf], ah[mt], bb[nf]);
        }
        __syncthreads();
    }

    // ---------------- epilogue ----------------
    const int er = lane >> 2, ec = (lane & 3) * 2;
    if (EPI == 1){
        // stage transposed tile in smem: s[d_local][kk_local], stride 136 halfs
        __half* s = reinterpret_cast<__half*>(dynsm + (tiles - smbase));
        __syncthreads();
        #pragma unroll
        for (int mt = 0; mt < 2; mt++)
            #pragma unroll
            for (int nf = 0; nf < 8; nf++){
                const int dn = wn * 64 + nf * 8 + ec;
                #pragma unroll
                for (int rr = 0; rr < 2; rr++){
                    const int km = wm * 32 + mt * 16 + er + rr * 8;
                    s[(size_t)dn * 136 + km]     = __float2half(acc[mt][nf][rr*2]);
                    s[(size_t)(dn+1) * 136 + km] = __float2half(acc[mt][nf][rr*2+1]);
                }
            }
        __syncthreads();
        const int batch = m0 / KLEN;
        const int kkb   = m0 % KLEN;
        #pragma unroll
        for (int pass = 0; pass < 8; pass++){
            int drow = (tid >> 4) + pass * 16;          // 0..127
            int seg  = tid & 15;                        // 16 x 8 halfs = 128
            uint4 v = *reinterpret_cast<const uint4*>(s + (size_t)drow * 136 + seg * 8);
            *reinterpret_cast<uint4*>(C16 + ((size_t)batch * EMBED + n0 + drow) * KLEN + kkb + seg * 8) = v;
        }
        return;
    }
    #pragma unroll
    for (int mt = 0; mt < 2; mt++)
        #pragma unroll
        for (int nf = 0; nf < 8; nf++){
            const int n = n0 + wn * 64 + nf * 8 + ec;
            #pragma unroll
            for (int rr = 0; rr < 2; rr++){
                const int m = m0 + wm * 32 + mt * 16 + er + rr * 8;
                float v0 = acc[mt][nf][rr * 2] * scale, v1 = acc[mt][nf][rr * 2 + 1] * scale;
                if (EPI == 0){
                    __half2 hp = __floats2half2_rn(v0, v1);
                    *reinterpret_cast<uint32_t*>(C16 + (size_t)m * ldc + n) = *reinterpret_cast<uint32_t*>(&hp);
                } else {
                    size_t off = (size_t)m * ldc + n;
                    float2 rv = *reinterpret_cast<const float2*>(resid + off);
                    float2 bv = *reinterpret_cast<const float2*>(bias + n);
                    float2 o; o.x = v0 + rv.x + bv.x; o.y = v1 + rv.y + bv.y;
                    *reinterpret_cast<float2*>(Cf + off) = o;
                }
            }
        }
}

// ---------------- converts ----------------
__global__ void __launch_bounds__(256, 1)
cvt16(const float* __restrict__ in, __half* __restrict__ out, int n)
{
    int i = (blockIdx.x * 256 + threadIdx.x) * 4;
    if (i >= n) return;
    float4 v = *reinterpret_cast<const float4*>(in + i);
    __half2 a = __floats2half2_rn(v.x, v.y);
    __half2 b = __floats2half2_rn(v.z, v.w);
    uint2 o;
    o.x = *reinterpret_cast<uint32_t*>(&a);
    o.y = *reinterpret_cast<uint32_t*>(&b);
    *reinterpret_cast<uint2*>(out + i) = o;
}
__global__ void __launch_bounds__(256, 1)
cvtW(const float* __restrict__ w0, const float* __restrict__ w1,
     const float* __restrict__ w2, const float* __restrict__ w3,
     __half* __restrict__ out)
{
    const float* src = (blockIdx.y == 0) ? w0 : (blockIdx.y == 1) ? w1 : (blockIdx.y == 2) ? w2 : w3;
    __half* dst = out + (size_t)blockIdx.y * EMBED * EMBED;
    int i = (blockIdx.x * 256 + threadIdx.x) * 4;
    float4 v = *reinterpret_cast<const float4*>(src + i);
    __half2 a = __floats2half2_rn(v.x, v.y);
    __half2 b = __floats2half2_rn(v.z, v.w);
    uint2 o;
    o.x = *reinterpret_cast<uint32_t*>(&a);
    o.y = *reinterpret_cast<uint32_t*>(&b);
    *reinterpret_cast<uint2*>(dst + i) = o;
}

// ---------------- fp16 row softmax (scale pre-applied in QK epilogue) ----------------
__inline__ __device__ float wmax(float v){
    #pragma unroll
    for (int o = 16; o; o >>= 1) v = fmaxf(v, __shfl_xor_sync(0xffffffffu, v, o));
    return v;
}
__inline__ __device__ float wsum(float v){
    #pragma unroll
    for (int o = 16; o; o >>= 1) v += __shfl_xor_sync(0xffffffffu, v, o);
    return v;
}
__global__ void __launch_bounds__(256, 1)
softmax16(__half* __restrict__ E)
{
    const size_t base = (size_t)blockIdx.x * KLEN;
    const int t = threadIdx.x;
    __shared__ float red[8];

    float v[16];
    #pragma unroll
    for (int i = 0; i < 2; i++){
        uint4 u = *reinterpret_cast<const uint4*>(E + base + (size_t)(t + i*256) * 8);
        const __half* hp = reinterpret_cast<const __half*>(&u);
        #pragma unroll
        for (int k = 0; k < 8; k++) v[i*8+k] = __half2float(hp[k]);
    }
    float mx = -INFINITY;
    #pragma unroll
    for (int i = 0; i < 16; i++) mx = fmaxf(mx, v[i]);
    mx = wmax(mx);
    if ((t & 31) == 0) red[t >> 5] = mx;
    __syncthreads();
    if (t < 32){ float m = (t < 8) ? red[t] : -INFINITY; m = wmax(m); if (!t) red[0] = m; }
    __syncthreads();
    mx = red[0];
    __syncthreads();
    float sum = 0.f;
    #pragma unroll
    for (int i = 0; i < 16; i++){ v[i] = __expf(v[i] - mx); sum += v[i]; }
    sum = wsum(sum);
    if ((t & 31) == 0) red[t >> 5] = sum;
    __syncthreads();
    if (t < 32){ float s = (t < 8) ? red[t] : 0.f; s = wsum(s); if (!t) red[0] = s; }
    __syncthreads();
    const float inv = 1.f / red[0];
    #pragma unroll
    for (int i = 0; i < 2; i++){
        __align__(16) __half hb[8];
        #pragma unroll
        for (int k = 0; k < 8; k++) hb[k] = __float2half(v[i*8+k] * inv);
        *reinterpret_cast<uint4*>(E + base + (size_t)(t + i*256) * 8) = *reinterpret_cast<const uint4*>(hb);
    }
}

// ---------------- launch ----------------
extern "C" void kernel_launch(void* const* d_in, const int* in_sizes, int n_in,
                              void* d_out, int out_size)
{
    const float* x  = (const float*)d_in[0];
    const float* y  = (const float*)d_in[1];
    const float* Wq = (const float*)d_in[2];
    const float* Wk = (const float*)d_in[3];
    const float* Wv = (const float*)d_in[4];
    const float* Wo = (const float*)d_in[5];
    const float* bo = (const float*)d_in[6];
    float* out = (float*)d_out;

    __half *x16,*y16,*W16,*Q16,*K16,*Vt16,*E16,*O16;
    cudaGetSymbolAddress((void**)&x16,  g_x16);
    cudaGetSymbolAddress((void**)&y16,  g_y16);
    cudaGetSymbolAddress((void**)&W16,  g_W16);
    cudaGetSymbolAddress((void**)&Q16,  g_Q16);
    cudaGetSymbolAddress((void**)&K16,  g_K16);
    cudaGetSymbolAddress((void**)&Vt16, g_Vt16);
    cudaGetSymbolAddress((void**)&E16,  g_E16);
    cudaGetSymbolAddress((void**)&O16,  g_O16);
    __half* wq16 = W16;
    __half* wk16 = W16 + (size_t)EMBED*EMBED;
    __half* wv16 = W16 + (size_t)2*EMBED*EMBED;
    __half* wo16 = W16 + (size_t)3*EMBED*EMBED;
    cudaFuncSetAttribute(gemm2<0>, cudaFuncAttributeMaxDynamicSharedMemorySize, GSMEM);
    cudaFuncSetAttribute(gemm2<1>, cudaFuncAttributeMaxDynamicSharedMemorySize, GSMEM);
    cudaFuncSetAttribute(gemm2<2>, cudaFuncAttributeMaxDynamicSharedMemorySize, GSMEM);

    const float sc = 1.0f / sqrtf((float)EMBED);

    cvt16<<<MQ*EMBED/1024, 256>>>(x, x16, MQ*EMBED);
    cvt16<<<MK*EMBED/1024, 256>>>(y, y16, MK*EMBED);
    cvtW<<<dim3(EMBED*EMBED/1024, 4), 256>>>(Wq, Wk, Wv, Wo, W16);

    // Q = x @ Wq^T
    gemm2<0><<<dim3(EMBED/128, MQ/128, 1), 256, GSMEM>>>(
        x16, 0, EMBED, wq16, 0, EMBED, EMBED, Q16, 0, EMBED, nullptr, nullptr, nullptr, 1.0f);
    // K = y @ Wk^T
    gemm2<0><<<dim3(EMBED/128, MK/128, 1), 256, GSMEM>>>(
        y16, 0, EMBED, wk16, 0, EMBED, EMBED, K16, 0, EMBED, nullptr, nullptr, nullptr, 1.0f);
    // V = y @ Wv^T, transposed epilogue -> Vt[b][d][kk]
    gemm2<1><<<dim3(EMBED/128, MK/128, 1), 256, GSMEM>>>(
        y16, 0, EMBED, wv16, 0, EMBED, EMBED, Vt16, 0, 0, nullptr, nullptr, nullptr, 1.0f);
    // E_b = (Q_b @ K_b^T) * sc
    gemm2<0><<<dim3(KLEN/128, QLEN/128, NBATCH), 256, GSMEM>>>(
        Q16, (long long)QLEN*EMBED, EMBED,
        K16, (long long)KLEN*EMBED, EMBED, EMBED,
        E16, (long long)QLEN*KLEN, KLEN, nullptr, nullptr, nullptr, sc);
    // softmax rows in place
    softmax16<<<MQ, 256>>>(E16);
    // O_b = P_b @ Vt_b^T
    gemm2<0><<<dim3(EMBED/128, QLEN/128, NBATCH), 256, GSMEM>>>(
        E16, (long long)QLEN*KLEN, KLEN,
        Vt16, (long long)EMBED*KLEN, KLEN, KLEN,
        O16, (long long)QLEN*EMBED, EMBED, nullptr, nullptr, nullptr, 1.0f);
    // out = x + O @ Wo^T + bo
    gemm2<2><<<dim3(EMBED/128, MQ/128, 1), 256, GSMEM>>>(
        O16, 0, EMBED, wo16, 0, EMBED, EMBED,
        nullptr, 0, EMBED, out, x, bo, 1.0f);
}

// round 8
// speedup vs baseline: 7.8259x; 1.0700x over previous
#include <cuda_runtime.h>
#include <cuda_fp16.h>
#include <stdint.h>
#include <math.h>

#define EMBED 512
#define NBATCH 8
#define QLEN 2048
#define KLEN 4096
#define MQ (NBATCH*QLEN)
#define MK (NBATCH*KLEN)

__device__ __half g_x16[MQ*EMBED];
__device__ __half g_y16[MK*EMBED];
__device__ __half g_W16[4][EMBED*EMBED];     // q,k,v,o
__device__ __half g_Q16[MQ*EMBED];
__device__ __half g_K16[MK*EMBED];
__device__ __half g_Vt16[(size_t)NBATCH*EMBED*KLEN];
__device__ __half g_E16[(size_t)MQ*KLEN];
__device__ __half g_O16[MQ*EMBED];

__device__ __forceinline__ uint32_t smem_u32(const void* p){
    uint32_t a;
    asm("{ .reg .u64 t; cvta.to.shared.u64 t, %1; cvt.u32.u64 %0, t; }" : "=r"(a) : "l"(p));
    return a;
}
#define CP16(s,g)   asm volatile("cp.async.cg.shared.global [%0], [%1], 16;" :: "r"(s), "l"(g) : "memory")
#define CP_COMMIT() asm volatile("cp.async.commit_group;" ::: "memory")
#define CP_WAIT1()  asm volatile("cp.async.wait_group 1;" ::: "memory")
#define CP_WAIT0()  asm volatile("cp.async.wait_group 0;" ::: "memory")

__device__ __forceinline__ void ldm4(uint32_t* r, uint32_t a){
    asm volatile("ldmatrix.sync.aligned.m8n8.x4.shared.b16 {%0,%1,%2,%3}, [%4];"
        : "=r"(r[0]), "=r"(r[1]), "=r"(r[2]), "=r"(r[3]) : "r"(a));
}
__device__ __forceinline__ void mma_f16(float* c, const uint32_t* a, const uint32_t* b){
    asm volatile("mma.sync.aligned.m16n8k16.row.col.f32.f16.f16.f32 "
        "{%0,%1,%2,%3}, {%4,%5,%6,%7}, {%8,%9}, {%0,%1,%2,%3};"
        : "+f"(c[0]), "+f"(c[1]), "+f"(c[2]), "+f"(c[3])
        : "r"(a[0]), "r"(a[1]), "r"(a[2]), "r"(a[3]), "r"(b[0]), "r"(b[1]));
}

// ---------------- fp16 mma.sync GEMM, tile 128x128x64-stage, 3-stage, 1 sync/stage ----------------
// D[m][n] = sum_k A[m][k]*B[n][k].  8 warps = 4(m) x 2(n); warp tile 32x64.
// Stage = k64: A 16KB + B 16KB (128B rows, 8-chunk XOR swizzle).
// EPI 0: fp16 out (scaled).  EPI 1: V-transpose epilogue -> Vt[b][d][kk].
// EPI 2: f32 out = acc + resid + bias.
#define STAGE_B 32768
#define GSMEM   (3*STAGE_B + 1024)

template<int EPI>
__global__ void __launch_bounds__(256, 2)
gemm2(const __half* __restrict__ A, long long sA, int lda,
      const __half* __restrict__ B, long long sB, int ldb,
      int Kdim,
      __half* __restrict__ C16, long long sC, int ldc,
      float* __restrict__ Cf, const float* __restrict__ resid,
      const float* __restrict__ bias, float scale)
{
    extern __shared__ char dynsm[];
    const uint32_t smbase = smem_u32(dynsm);
    const uint32_t tiles = (smbase + 1023u) & ~1023u;
    const int tid = threadIdx.x, lane = tid & 31, wid = tid >> 5;
    const int wm = wid & 3, wn = wid >> 2;
    const int m0 = blockIdx.y * 128, n0 = blockIdx.x * 128, b = blockIdx.z;
    A += (size_t)b * sA;  B += (size_t)b * sB;
    if (EPI == 0) C16 += (size_t)b * sC;

    float acc[2][8][4];
    #pragma unroll
    for (int i = 0; i < 2; i++)
        #pragma unroll
        for (int j = 0; j < 8; j++)
            #pragma unroll
            for (int k = 0; k < 4; k++) acc[i][j][k] = 0.f;

    // ldmatrix addressing: 128B rows = 8x16B chunks, swizzle ch ^= (row&7)
    const int r_lane = (lane & 7) + ((lane >> 3) & 1) * 8;
    uint32_t aRow[2], aSw[2];
    #pragma unroll
    for (int mt = 0; mt < 2; mt++){
        int m_loc = wm * 32 + mt * 16 + r_lane;
        aRow[mt] = (uint32_t)(m_loc * 128);
        aSw[mt]  = (uint32_t)(m_loc & 7);
    }
    const uint32_t aCk = (lane >> 4) & 1;
    uint32_t bRow[4], bSw[4];
    {
        int n_base = wn * 64 + ((lane >> 4) & 1) * 8 + (lane & 7);
        #pragma unroll
        for (int g = 0; g < 4; g++){
            int n_loc = n_base + g * 16;
            bRow[g] = (uint32_t)(n_loc * 128);
            bSw[g]  = (uint32_t)(n_loc & 7);
        }
    }
    const uint32_t bCk = (lane >> 3) & 1;

    const int C = Kdim >> 6;   // k64 stages (Kdim is 512 or 4096)

    auto load_stage = [&](int c){
        const uint32_t sb = tiles + (c % 3) * STAGE_B;
        const int k0 = c << 6;
        #pragma unroll
        for (int i = 0; i < 4; i++){           // A: 128 rows x 8 chunks
            int idx = tid + i * 256;
            int row = idx >> 3, ch = idx & 7;
            uint32_t so = (uint32_t)(row * 128 + ((ch ^ (row & 7)) << 4));
            CP16(sb + so, A + (size_t)(m0 + row) * lda + k0 + ch * 8);
        }
        #pragma unroll
        for (int i = 0; i < 4; i++){           // B: 128 rows x 8 chunks
            int idx = tid + i * 256;
            int row = idx >> 3, ch = idx & 7;
            uint32_t so = (uint32_t)(row * 128 + ((ch ^ (row & 7)) << 4));
            CP16(sb + 16384 + so, B + (size_t)(n0 + row) * ldb + k0 + ch * 8);
        }
    };

    load_stage(0); CP_COMMIT();
    load_stage(1); CP_COMMIT();

    for (int c = 0; c < C; c++){
        if (c < C - 1) CP_WAIT1(); else CP_WAIT0();
        __syncthreads();
        // single barrier: stage c ready AND all warps done reading slot (c-1)%3,
        // so the next load (slot (c+2)%3 == (c-1)%3) is safe to issue now.
        if (c + 2 < C){ load_stage(c + 2); CP_COMMIT(); }

        const uint32_t sb = tiles + (c % 3) * STAGE_B;
        #pragma unroll
        for (int ks = 0; ks < 4; ks++){
            uint32_t ah[2][4];
            #pragma unroll
            for (int mt = 0; mt < 2; mt++){
                uint32_t off = aRow[mt] + ((((uint32_t)(2 * ks) + aCk) ^ aSw[mt]) << 4);
                ldm4(ah[mt], sb + off);
            }
            uint32_t bb[8][2];
            #pragma unroll
            for (int g = 0; g < 4; g++){
                uint32_t off = bRow[g] + ((((uint32_t)(2 * ks) + bCk) ^ bSw[g]) << 4);
                uint32_t q[4];
                ldm4(q, sb + 16384 + off);
                bb[2*g][0]=q[0]; bb[2*g][1]=q[1]; bb[2*g+1][0]=q[2]; bb[2*g+1][1]=q[3];
            }
            #pragma unroll
            for (int mt = 0; mt < 2; mt++)
                #pragma unroll
                for (int nf = 0; nf < 8; nf++)
                    mma_f16(acc[mt][nf], ah[mt], bb[nf]);
        }
    }

    // ---------------- epilogue ----------------
    const int er = lane >> 2, ec = (lane & 3) * 2;
    if (EPI == 1){
        // stage transposed tile in smem: s[d_local][kk_local], stride 136 halfs
        __half* s = reinterpret_cast<__half*>(dynsm + (tiles - smbase));
        __syncthreads();
        #pragma unroll
        for (int mt = 0; mt < 2; mt++)
            #pragma unroll
            for (int nf = 0; nf < 8; nf++){
                const int dn = wn * 64 + nf * 8 + ec;
                #pragma unroll
                for (int rr = 0; rr < 2; rr++){
                    const int km = wm * 32 + mt * 16 + er + rr * 8;
                    s[(size_t)dn * 136 + km]     = __float2half(acc[mt][nf][rr*2]);
                    s[(size_t)(dn+1) * 136 + km] = __float2half(acc[mt][nf][rr*2+1]);
                }
            }
        __syncthreads();
        const int batch = m0 / KLEN;
        const int kkb   = m0 % KLEN;
        #pragma unroll
        for (int pass = 0; pass < 8; pass++){
            int drow = (tid >> 4) + pass * 16;          // 0..127
            int seg  = tid & 15;                        // 16 x 8 halfs = 128
            uint4 v = *reinterpret_cast<const uint4*>(s + (size_t)drow * 136 + seg * 8);
            *reinterpret_cast<uint4*>(C16 + ((size_t)batch * EMBED + n0 + drow) * KLEN + kkb + seg * 8) = v;
        }
        return;
    }
    #pragma unroll
    for (int mt = 0; mt < 2; mt++)
        #pragma unroll
        for (int nf = 0; nf < 8; nf++){
            const int n = n0 + wn * 64 + nf * 8 + ec;
            #pragma unroll
            for (int rr = 0; rr < 2; rr++){
                const int m = m0 + wm * 32 + mt * 16 + er + rr * 8;
                float v0 = acc[mt][nf][rr * 2] * scale, v1 = acc[mt][nf][rr * 2 + 1] * scale;
                if (EPI == 0){
                    __half2 hp = __floats2half2_rn(v0, v1);
                    *reinterpret_cast<uint32_t*>(C16 + (size_t)m * ldc + n) = *reinterpret_cast<uint32_t*>(&hp);
                } else {
                    size_t off = (size_t)m * ldc + n;
                    float2 rv = *reinterpret_cast<const float2*>(resid + off);
                    float2 bv = *reinterpret_cast<const float2*>(bias + n);
                    float2 o; o.x = v0 + rv.x + bv.x; o.y = v1 + rv.y + bv.y;
                    *reinterpret_cast<float2*>(Cf + off) = o;
                }
            }
        }
}

// ---------------- converts ----------------
__global__ void __launch_bounds__(256, 1)
cvt16(const float* __restrict__ in, __half* __restrict__ out, int n)
{
    int i = (blockIdx.x * 256 + threadIdx.x) * 4;
    if (i >= n) return;
    float4 v = *reinterpret_cast<const float4*>(in + i);
    __half2 a = __floats2half2_rn(v.x, v.y);
    __half2 b = __floats2half2_rn(v.z, v.w);
    uint2 o;
    o.x = *reinterpret_cast<uint32_t*>(&a);
    o.y = *reinterpret_cast<uint32_t*>(&b);
    *reinterpret_cast<uint2*>(out + i) = o;
}
__global__ void __launch_bounds__(256, 1)
cvtW(const float* __restrict__ w0, const float* __restrict__ w1,
     const float* __restrict__ w2, const float* __restrict__ w3,
     __half* __restrict__ out)
{
    const float* src = (blockIdx.y == 0) ? w0 : (blockIdx.y == 1) ? w1 : (blockIdx.y == 2) ? w2 : w3;
    __half* dst = out + (size_t)blockIdx.y * EMBED * EMBED;
    int i = (blockIdx.x * 256 + threadIdx.x) * 4;
    float4 v = *reinterpret_cast<const float4*>(src + i);
    __half2 a = __floats2half2_rn(v.x, v.y);
    __half2 b = __floats2half2_rn(v.z, v.w);
    uint2 o;
    o.x = *reinterpret_cast<uint32_t*>(&a);
    o.y = *reinterpret_cast<uint32_t*>(&b);
    *reinterpret_cast<uint2*>(dst + i) = o;
}

// ---------------- fp16 row softmax (scale pre-applied in QK epilogue) ----------------
__inline__ __device__ float wmax(float v){
    #pragma unroll
    for (int o = 16; o; o >>= 1) v = fmaxf(v, __shfl_xor_sync(0xffffffffu, v, o));
    return v;
}
__inline__ __device__ float wsum(float v){
    #pragma unroll
    for (int o = 16; o; o >>= 1) v += __shfl_xor_sync(0xffffffffu, v, o);
    return v;
}
__global__ void __launch_bounds__(256, 1)
softmax16(__half* __restrict__ E)
{
    const size_t base = (size_t)blockIdx.x * KLEN;
    const int t = threadIdx.x;
    __shared__ float red[8];

    float v[16];
    #pragma unroll
    for (int i = 0; i < 2; i++){
        uint4 u = *reinterpret_cast<const uint4*>(E + base + (size_t)(t + i*256) * 8);
        const __half* hp = reinterpret_cast<const __half*>(&u);
        #pragma unroll
        for (int k = 0; k < 8; k++) v[i*8+k] = __half2float(hp[k]);
    }
    float mx = -INFINITY;
    #pragma unroll
    for (int i = 0; i < 16; i++) mx = fmaxf(mx, v[i]);
    mx = wmax(mx);
    if ((t & 31) == 0) red[t >> 5] = mx;
    __syncthreads();
    if (t < 32){ float m = (t < 8) ? red[t] : -INFINITY; m = wmax(m); if (!t) red[0] = m; }
    __syncthreads();
    mx = red[0];
    __syncthreads();
    float sum = 0.f;
    #pragma unroll
    for (int i = 0; i < 16; i++){ v[i] = __expf(v[i] - mx); sum += v[i]; }
    sum = wsum(sum);
    if ((t & 31) == 0) red[t >> 5] = sum;
    __syncthreads();
    if (t < 32){ float s = (t < 8) ? red[t] : 0.f; s = wsum(s); if (!t) red[0] = s; }
    __syncthreads();
    const float inv = 1.f / red[0];
    #pragma unroll
    for (int i = 0; i < 2; i++){
        __align__(16) __half hb[8];
        #pragma unroll
        for (int k = 0; k < 8; k++) hb[k] = __float2half(v[i*8+k] * inv);
        *reinterpret_cast<uint4*>(E + base + (size_t)(t + i*256) * 8) = *reinterpret_cast<const uint4*>(hb);
    }
}

// ---------------- launch ----------------
extern "C" void kernel_launch(void* const* d_in, const int* in_sizes, int n_in,
                              void* d_out, int out_size)
{
    const float* x  = (const float*)d_in[0];
    const float* y  = (const float*)d_in[1];
    const float* Wq = (const float*)d_in[2];
    const float* Wk = (const float*)d_in[3];
    const float* Wv = (const float*)d_in[4];
    const float* Wo = (const float*)d_in[5];
    const float* bo = (const float*)d_in[6];
    float* out = (float*)d_out;

    __half *x16,*y16,*W16,*Q16,*K16,*Vt16,*E16,*O16;
    cudaGetSymbolAddress((void**)&x16,  g_x16);
    cudaGetSymbolAddress((void**)&y16,  g_y16);
    cudaGetSymbolAddress((void**)&W16,  g_W16);
    cudaGetSymbolAddress((void**)&Q16,  g_Q16);
    cudaGetSymbolAddress((void**)&K16,  g_K16);
    cudaGetSymbolAddress((void**)&Vt16, g_Vt16);
    cudaGetSymbolAddress((void**)&E16,  g_E16);
    cudaGetSymbolAddress((void**)&O16,  g_O16);
    __half* wq16 = W16;
    __half* wk16 = W16 + (size_t)EMBED*EMBED;
    __half* wv16 = W16 + (size_t)2*EMBED*EMBED;
    __half* wo16 = W16 + (size_t)3*EMBED*EMBED;
    cudaFuncSetAttribute(gemm2<0>, cudaFuncAttributeMaxDynamicSharedMemorySize, GSMEM);
    cudaFuncSetAttribute(gemm2<1>, cudaFuncAttributeMaxDynamicSharedMemorySize, GSMEM);
    cudaFuncSetAttribute(gemm2<2>, cudaFuncAttributeMaxDynamicSharedMemorySize, GSMEM);

    const float sc = 1.0f / sqrtf((float)EMBED);

    cvt16<<<MQ*EMBED/1024, 256>>>(x, x16, MQ*EMBED);
    cvt16<<<MK*EMBED/1024, 256>>>(y, y16, MK*EMBED);
    cvtW<<<dim3(EMBED*EMBED/1024, 4), 256>>>(Wq, Wk, Wv, Wo, W16);

    // Q = x @ Wq^T
    gemm2<0><<<dim3(EMBED/128, MQ/128, 1), 256, GSMEM>>>(
        x16, 0, EMBED, wq16, 0, EMBED, EMBED, Q16, 0, EMBED, nullptr, nullptr, nullptr, 1.0f);
    // K = y @ Wk^T
    gemm2<0><<<dim3(EMBED/128, MK/128, 1), 256, GSMEM>>>(
        y16, 0, EMBED, wk16, 0, EMBED, EMBED, K16, 0, EMBED, nullptr, nullptr, nullptr, 1.0f);
    // V = y @ Wv^T, transposed epilogue -> Vt[b][d][kk]
    gemm2<1><<<dim3(EMBED/128, MK/128, 1), 256, GSMEM>>>(
        y16, 0, EMBED, wv16, 0, EMBED, EMBED, Vt16, 0, 0, nullptr, nullptr, nullptr, 1.0f);
    // E_b = (Q_b @ K_b^T) * sc
    gemm2<0><<<dim3(KLEN/128, QLEN/128, NBATCH), 256, GSMEM>>>(
        Q16, (long long)QLEN*EMBED, EMBED,
        K16, (long long)KLEN*EMBED, EMBED, EMBED,
        E16, (long long)QLEN*KLEN, KLEN, nullptr, nullptr, nullptr, sc);
    // softmax rows in place
    softmax16<<<MQ, 256>>>(E16);
    // O_b = P_b @ Vt_b^T
    gemm2<0><<<dim3(EMBED/128, QLEN/128, NBATCH), 256, GSMEM>>>(
        E16, (long long)QLEN*KLEN, KLEN,
        Vt16, (long long)EMBED*KLEN, KLEN, KLEN,
        O16, (long long)QLEN*EMBED, EMBED, nullptr, nullptr, nullptr, 1.0f);
    // out = x + O @ Wo^T + bo
    gemm2<2><<<dim3(EMBED/128, MQ/128, 1), 256, GSMEM>>>(
        O16, 0, EMBED, wo16, 0, EMBED, EMBED,
        nullptr, 0, EMBED, out, x, bo, 1.0f);
}

// round 9
// speedup vs baseline: 8.0825x; 1.0328x over previous
#include <cuda_runtime.h>
#include <cuda_fp16.h>
#include <stdint.h>
#include <math.h>

#define EMBED 512
#define NBATCH 8
#define QLEN 2048
#define KLEN 4096
#define MQ (NBATCH*QLEN)
#define MK (NBATCH*KLEN)
#define NBLK (KLEN/128)     // 32 partial sums per row

__device__ __half g_x16[MQ*EMBED];
__device__ __half g_y16[MK*EMBED];
__device__ __half g_W16[4][EMBED*EMBED];     // q,k,v,o
__device__ __half g_Q16[MQ*EMBED];
__device__ __half g_K16[MK*EMBED];
__device__ __half g_Vt16[(size_t)NBATCH*EMBED*KLEN];
__device__ __half g_E16[(size_t)MQ*KLEN];
__device__ __half g_O16[MQ*EMBED];
__device__ float  g_Esum[(size_t)MQ*NBLK];
__device__ float  g_inv[MQ];

__device__ __forceinline__ uint32_t smem_u32(const void* p){
    uint32_t a;
    asm("{ .reg .u64 t; cvta.to.shared.u64 t, %1; cvt.u32.u64 %0, t; }" : "=r"(a) : "l"(p));
    return a;
}
#define CP16(s,g)   asm volatile("cp.async.cg.shared.global [%0], [%1], 16;" :: "r"(s), "l"(g) : "memory")
#define CP_COMMIT() asm volatile("cp.async.commit_group;" ::: "memory")
#define CP_WAIT1()  asm volatile("cp.async.wait_group 1;" ::: "memory")
#define CP_WAIT0()  asm volatile("cp.async.wait_group 0;" ::: "memory")

__device__ __forceinline__ void ldm4(uint32_t* r, uint32_t a){
    asm volatile("ldmatrix.sync.aligned.m8n8.x4.shared.b16 {%0,%1,%2,%3}, [%4];"
        : "=r"(r[0]), "=r"(r[1]), "=r"(r[2]), "=r"(r[3]) : "r"(a));
}
__device__ __forceinline__ void mma_f16(float* c, const uint32_t* a, const uint32_t* b){
    asm volatile("mma.sync.aligned.m16n8k16.row.col.f32.f16.f16.f32 "
        "{%0,%1,%2,%3}, {%4,%5,%6,%7}, {%8,%9}, {%0,%1,%2,%3};"
        : "+f"(c[0]), "+f"(c[1]), "+f"(c[2]), "+f"(c[3])
        : "r"(a[0]), "r"(a[1]), "r"(a[2]), "r"(a[3]), "r"(b[0]), "r"(b[1]));
}

// ---------------- fp16 mma.sync GEMM, tile 128x128x64-stage, 3-stage, 1 sync/stage ----------------
// 8 warps = 4(m) x 2(n); warp tile 32x64.
// EPI 0: fp16 out (scaled).             EPI 1: V-transpose epilogue -> Vt[b][d][kk].
// EPI 2: f32 out = acc + resid + bias.  EPI 3: exp(scale*acc) fp16 + per-row partial sums.
// EPI 4: fp16 out * inv[row].
#define STAGE_B 32768
#define GSMEM   (3*STAGE_B + 1024)

template<int EPI>
__global__ void __launch_bounds__(256, 2)
gemm2(const __half* __restrict__ A, long long sA, int lda,
      const __half* __restrict__ B, long long sB, int ldb,
      int Kdim,
      __half* __restrict__ C16, long long sC, int ldc,
      float* __restrict__ Cf, const float* __restrict__ resid,
      const float* __restrict__ bias, float scale,
      float* __restrict__ Esum, const float* __restrict__ invs)
{
    extern __shared__ char dynsm[];
    const uint32_t smbase = smem_u32(dynsm);
    const uint32_t tiles = (smbase + 1023u) & ~1023u;
    const int tid = threadIdx.x, lane = tid & 31, wid = tid >> 5;
    const int wm = wid & 3, wn = wid >> 2;
    const int m0 = blockIdx.y * 128, n0 = blockIdx.x * 128, b = blockIdx.z;
    A += (size_t)b * sA;  B += (size_t)b * sB;
    if (EPI == 0 || EPI == 3 || EPI == 4) C16 += (size_t)b * sC;

    float acc[2][8][4];
    #pragma unroll
    for (int i = 0; i < 2; i++)
        #pragma unroll
        for (int j = 0; j < 8; j++)
            #pragma unroll
            for (int k = 0; k < 4; k++) acc[i][j][k] = 0.f;

    // ldmatrix addressing: 128B rows = 8x16B chunks, swizzle ch ^= (row&7)
    const int r_lane = (lane & 7) + ((lane >> 3) & 1) * 8;
    uint32_t aRow[2], aSw[2];
    #pragma unroll
    for (int mt = 0; mt < 2; mt++){
        int m_loc = wm * 32 + mt * 16 + r_lane;
        aRow[mt] = (uint32_t)(m_loc * 128);
        aSw[mt]  = (uint32_t)(m_loc & 7);
    }
    const uint32_t aCk = (lane >> 4) & 1;
    uint32_t bRow[4], bSw[4];
    {
        int n_base = wn * 64 + ((lane >> 4) & 1) * 8 + (lane & 7);
        #pragma unroll
        for (int g = 0; g < 4; g++){
            int n_loc = n_base + g * 16;
            bRow[g] = (uint32_t)(n_loc * 128);
            bSw[g]  = (uint32_t)(n_loc & 7);
        }
    }
    const uint32_t bCk = (lane >> 3) & 1;

    const int C = Kdim >> 6;

    auto load_stage = [&](int c){
        const uint32_t sb = tiles + (c % 3) * STAGE_B;
        const int k0 = c << 6;
        #pragma unroll
        for (int i = 0; i < 4; i++){
            int idx = tid + i * 256;
            int row = idx >> 3, ch = idx & 7;
            uint32_t so = (uint32_t)(row * 128 + ((ch ^ (row & 7)) << 4));
            CP16(sb + so, A + (size_t)(m0 + row) * lda + k0 + ch * 8);
        }
        #pragma unroll
        for (int i = 0; i < 4; i++){
            int idx = tid + i * 256;
            int row = idx >> 3, ch = idx & 7;
            uint32_t so = (uint32_t)(row * 128 + ((ch ^ (row & 7)) << 4));
            CP16(sb + 16384 + so, B + (size_t)(n0 + row) * ldb + k0 + ch * 8);
        }
    };

    load_stage(0); CP_COMMIT();
    load_stage(1); CP_COMMIT();

    for (int c = 0; c < C; c++){
        if (c < C - 1) CP_WAIT1(); else CP_WAIT0();
        __syncthreads();
        if (c + 2 < C){ load_stage(c + 2); CP_COMMIT(); }

        const uint32_t sb = tiles + (c % 3) * STAGE_B;
        #pragma unroll
        for (int ks = 0; ks < 4; ks++){
            uint32_t ah[2][4];
            #pragma unroll
            for (int mt = 0; mt < 2; mt++){
                uint32_t off = aRow[mt] + ((((uint32_t)(2 * ks) + aCk) ^ aSw[mt]) << 4);
                ldm4(ah[mt], sb + off);
            }
            uint32_t bb[8][2];
            #pragma unroll
            for (int g = 0; g < 4; g++){
                uint32_t off = bRow[g] + ((((uint32_t)(2 * ks) + bCk) ^ bSw[g]) << 4);
                uint32_t q[4];
                ldm4(q, sb + 16384 + off);
                bb[2*g][0]=q[0]; bb[2*g][1]=q[1]; bb[2*g+1][0]=q[2]; bb[2*g+1][1]=q[3];
            }
            #pragma unroll
            for (int mt = 0; mt < 2; mt++)
                #pragma unroll
                for (int nf = 0; nf < 8; nf++)
                    mma_f16(acc[mt][nf], ah[mt], bb[nf]);
        }
    }

    // ---------------- epilogue ----------------
    const int er = lane >> 2, ec = (lane & 3) * 2;
    if (EPI == 1){
        __half* s = reinterpret_cast<__half*>(dynsm + (tiles - smbase));
        __syncthreads();
        #pragma unroll
        for (int mt = 0; mt < 2; mt++)
            #pragma unroll
            for (int nf = 0; nf < 8; nf++){
                const int dn = wn * 64 + nf * 8 + ec;
                #pragma unroll
                for (int rr = 0; rr < 2; rr++){
                    const int km = wm * 32 + mt * 16 + er + rr * 8;
                    s[(size_t)dn * 136 + km]     = __float2half(acc[mt][nf][rr*2]);
                    s[(size_t)(dn+1) * 136 + km] = __float2half(acc[mt][nf][rr*2+1]);
                }
            }
        __syncthreads();
        const int batch = m0 / KLEN;
        const int kkb   = m0 % KLEN;
        #pragma unroll
        for (int pass = 0; pass < 8; pass++){
            int drow = (tid >> 4) + pass * 16;
            int seg  = tid & 15;
            uint4 v = *reinterpret_cast<const uint4*>(s + (size_t)drow * 136 + seg * 8);
            *reinterpret_cast<uint4*>(C16 + ((size_t)batch * EMBED + n0 + drow) * KLEN + kkb + seg * 8) = v;
        }
        return;
    }
    if (EPI == 3){
        // exp + store + per-row partial sums (deterministic)
        float* rs = reinterpret_cast<float*>(dynsm + (tiles - smbase));   // [2][128]
        float rowp[2][2] = {};
        #pragma unroll
        for (int mt = 0; mt < 2; mt++)
            #pragma unroll
            for (int nf = 0; nf < 8; nf++){
                const int n = n0 + wn * 64 + nf * 8 + ec;
                #pragma unroll
                for (int rr = 0; rr < 2; rr++){
                    const int m = m0 + wm * 32 + mt * 16 + er + rr * 8;
                    float e0 = __expf(acc[mt][nf][rr*2]   * scale);
                    float e1 = __expf(acc[mt][nf][rr*2+1] * scale);
                    __half2 hp = __floats2half2_rn(e0, e1);
                    *reinterpret_cast<uint32_t*>(C16 + (size_t)m * ldc + n) = *reinterpret_cast<uint32_t*>(&hp);
                    rowp[mt][rr] += e0 + e1;
                }
            }
        __syncthreads();   // tiles no longer needed; safe to reuse as rs
        // reduce across the 4 lanes sharing a row (lane = er*4 + 0..3)
        #pragma unroll
        for (int mt = 0; mt < 2; mt++)
            #pragma unroll
            for (int rr = 0; rr < 2; rr++){
                float v = rowp[mt][rr];
                v += __shfl_xor_sync(0xffffffffu, v, 1);
                v += __shfl_xor_sync(0xffffffffu, v, 2);
                if ((lane & 3) == 0){
                    int row = wm * 32 + mt * 16 + rr * 8 + er;
                    rs[wn * 128 + row] = v;
                }
            }
        __syncthreads();
        if (tid < 128){
            float s = rs[tid] + rs[128 + tid];
            Esum[((size_t)b * QLEN + m0 + tid) * NBLK + blockIdx.x] = s;
        }
        return;
    }
    #pragma unroll
    for (int mt = 0; mt < 2; mt++)
        #pragma unroll
        for (int nf = 0; nf < 8; nf++){
            const int n = n0 + wn * 64 + nf * 8 + ec;
            #pragma unroll
            for (int rr = 0; rr < 2; rr++){
                const int m = m0 + wm * 32 + mt * 16 + er + rr * 8;
                float v0 = acc[mt][nf][rr * 2], v1 = acc[mt][nf][rr * 2 + 1];
                if (EPI == 4){
                    float inv = invs[(size_t)b * QLEN + m];
                    v0 *= inv; v1 *= inv;
                } else {
                    v0 *= scale; v1 *= scale;
                }
                if (EPI == 0 || EPI == 4){
                    __half2 hp = __floats2half2_rn(v0, v1);
                    *reinterpret_cast<uint32_t*>(C16 + (size_t)m * ldc + n) = *reinterpret_cast<uint32_t*>(&hp);
                } else {
                    size_t off = (size_t)m * ldc + n;
                    float2 rv = *reinterpret_cast<const float2*>(resid + off);
                    float2 bv = *reinterpret_cast<const float2*>(bias + n);
                    float2 o; o.x = v0 + rv.x + bv.x; o.y = v1 + rv.y + bv.y;
                    *reinterpret_cast<float2*>(Cf + off) = o;
                }
            }
        }
}

// ---------------- converts ----------------
__global__ void __launch_bounds__(256, 1)
cvt16(const float* __restrict__ in, __half* __restrict__ out, int n)
{
    int i = (blockIdx.x * 256 + threadIdx.x) * 4;
    if (i >= n) return;
    float4 v = *reinterpret_cast<const float4*>(in + i);
    __half2 a = __floats2half2_rn(v.x, v.y);
    __half2 b = __floats2half2_rn(v.z, v.w);
    uint2 o;
    o.x = *reinterpret_cast<uint32_t*>(&a);
    o.y = *reinterpret_cast<uint32_t*>(&b);
    *reinterpret_cast<uint2*>(out + i) = o;
}
__global__ void __launch_bounds__(256, 1)
cvtW(const float* __restrict__ w0, const float* __restrict__ w1,
     const float* __restrict__ w2, const float* __restrict__ w3,
     __half* __restrict__ out)
{
    const float* src = (blockIdx.y == 0) ? w0 : (blockIdx.y == 1) ? w1 : (blockIdx.y == 2) ? w2 : w3;
    __half* dst = out + (size_t)blockIdx.y * EMBED * EMBED;
    int i = (blockIdx.x * 256 + threadIdx.x) * 4;
    float4 v = *reinterpret_cast<const float4*>(src + i);
    __half2 a = __floats2half2_rn(v.x, v.y);
    __half2 b = __floats2half2_rn(v.z, v.w);
    uint2 o;
    o.x = *reinterpret_cast<uint32_t*>(&a);
    o.y = *reinterpret_cast<uint32_t*>(&b);
    *reinterpret_cast<uint2*>(dst + i) = o;
}

// ---------------- fold 32 partial sums -> 1/sum per row ----------------
__global__ void __launch_bounds__(256, 1)
rowinv(const float* __restrict__ Esum, float* __restrict__ invs)
{
    int r = blockIdx.x * 256 + threadIdx.x;
    float s = 0.f;
    #pragma unroll
    for (int i = 0; i < NBLK; i++) s += Esum[(size_t)r * NBLK + i];
    invs[r] = 1.f / s;
}

// ---------------- launch ----------------
extern "C" void kernel_launch(void* const* d_in, const int* in_sizes, int n_in,
                              void* d_out, int out_size)
{
    const float* x  = (const float*)d_in[0];
    const float* y  = (const float*)d_in[1];
    const float* Wq = (const float*)d_in[2];
    const float* Wk = (const float*)d_in[3];
    const float* Wv = (const float*)d_in[4];
    const float* Wo = (const float*)d_in[5];
    const float* bo = (const float*)d_in[6];
    float* out = (float*)d_out;

    __half *x16,*y16,*W16,*Q16,*K16,*Vt16,*E16,*O16;
    float *Esum,*invs;
    cudaGetSymbolAddress((void**)&x16,  g_x16);
    cudaGetSymbolAddress((void**)&y16,  g_y16);
    cudaGetSymbolAddress((void**)&W16,  g_W16);
    cudaGetSymbolAddress((void**)&Q16,  g_Q16);
    cudaGetSymbolAddress((void**)&K16,  g_K16);
    cudaGetSymbolAddress((void**)&Vt16, g_Vt16);
    cudaGetSymbolAddress((void**)&E16,  g_E16);
    cudaGetSymbolAddress((void**)&O16,  g_O16);
    cudaGetSymbolAddress((void**)&Esum, g_Esum);
    cudaGetSymbolAddress((void**)&invs, g_inv);
    __half* wq16 = W16;
    __half* wk16 = W16 + (size_t)EMBED*EMBED;
    __half* wv16 = W16 + (size_t)2*EMBED*EMBED;
    __half* wo16 = W16 + (size_t)3*EMBED*EMBED;
    cudaFuncSetAttribute(gemm2<0>, cudaFuncAttributeMaxDynamicSharedMemorySize, GSMEM);
    cudaFuncSetAttribute(gemm2<1>, cudaFuncAttributeMaxDynamicSharedMemorySize, GSMEM);
    cudaFuncSetAttribute(gemm2<2>, cudaFuncAttributeMaxDynamicSharedMemorySize, GSMEM);
    cudaFuncSetAttribute(gemm2<3>, cudaFuncAttributeMaxDynamicSharedMemorySize, GSMEM);
    cudaFuncSetAttribute(gemm2<4>, cudaFuncAttributeMaxDynamicSharedMemorySize, GSMEM);

    const float sc = 1.0f / sqrtf((float)EMBED);

    cvt16<<<MQ*EMBED/1024, 256>>>(x, x16, MQ*EMBED);
    cvt16<<<MK*EMBED/1024, 256>>>(y, y16, MK*EMBED);
    cvtW<<<dim3(EMBED*EMBED/1024, 4), 256>>>(Wq, Wk, Wv, Wo, W16);

    // Q = x @ Wq^T
    gemm2<0><<<dim3(EMBED/128, MQ/128, 1), 256, GSMEM>>>(
        x16, 0, EMBED, wq16, 0, EMBED, EMBED, Q16, 0, EMBED,
        nullptr, nullptr, nullptr, 1.0f, nullptr, nullptr);
    // K = y @ Wk^T
    gemm2<0><<<dim3(EMBED/128, MK/128, 1), 256, GSMEM>>>(
        y16, 0, EMBED, wk16, 0, EMBED, EMBED, K16, 0, EMBED,
        nullptr, nullptr, nullptr, 1.0f, nullptr, nullptr);
    // V = y @ Wv^T, transposed epilogue -> Vt[b][d][kk]
    gemm2<1><<<dim3(EMBED/128, MK/128, 1), 256, GSMEM>>>(
        y16, 0, EMBED, wv16, 0, EMBED, EMBED, Vt16, 0, 0,
        nullptr, nullptr, nullptr, 1.0f, nullptr, nullptr);
    // E_b = exp(sc * Q_b @ K_b^T), plus per-row partial sums
    gemm2<3><<<dim3(KLEN/128, QLEN/128, NBATCH), 256, GSMEM>>>(
        Q16, (long long)QLEN*EMBED, EMBED,
        K16, (long long)KLEN*EMBED, EMBED, EMBED,
        E16, (long long)QLEN*KLEN, KLEN,
        nullptr, nullptr, nullptr, sc, Esum, nullptr);
    // inv[row] = 1 / sum
    rowinv<<<MQ/256, 256>>>(Esum, invs);
    // O_b = (E_b @ Vt_b^T) * inv[row]
    gemm2<4><<<dim3(EMBED/128, QLEN/128, NBATCH), 256, GSMEM>>>(
        E16, (long long)QLEN*KLEN, KLEN,
        Vt16, (long long)EMBED*KLEN, KLEN, KLEN,
        O16, (long long)QLEN*EMBED, EMBED,
        nullptr, nullptr, nullptr, 1.0f, nullptr, invs);
    // out = x + O @ Wo^T + bo
    gemm2<2><<<dim3(EMBED/128, MQ/128, 1), 256, GSMEM>>>(
        O16, 0, EMBED, wo16, 0, EMBED, EMBED,
        nullptr, 0, EMBED, out, x, bo, 1.0f, nullptr, nullptr);
}

// round 10
// speedup vs baseline: 8.5300x; 1.0554x over previous
#include <cuda_runtime.h>
#include <cuda_fp16.h>
#include <stdint.h>
#include <math.h>

#define EMBED 512
#define NBATCH 8
#define QLEN 2048
#define KLEN 4096
#define MQ (NBATCH*QLEN)
#define MK (NBATCH*KLEN)
#define NBLK (KLEN/128)

__device__ __half g_x16[MQ*EMBED];
__device__ __half g_y16[MK*EMBED];
__device__ __half g_W16[4][EMBED*EMBED];     // q,k,v,o (contiguous)
__device__ __half g_Q16[MQ*EMBED];
__device__ __half g_K16[MK*EMBED];
__device__ __half g_Vt16[(size_t)NBATCH*EMBED*KLEN];
__device__ __half g_E16[(size_t)MQ*KLEN];
__device__ __half g_O16[MQ*EMBED];
__device__ float  g_Esum[(size_t)MQ*NBLK];

__device__ __forceinline__ uint32_t smem_u32(const void* p){
    uint32_t a;
    asm("{ .reg .u64 t; cvta.to.shared.u64 t, %1; cvt.u32.u64 %0, t; }" : "=r"(a) : "l"(p));
    return a;
}
#define CP16(s,g)   asm volatile("cp.async.cg.shared.global [%0], [%1], 16;" :: "r"(s), "l"(g) : "memory")
#define CP_COMMIT() asm volatile("cp.async.commit_group;" ::: "memory")
#define CP_WAIT1()  asm volatile("cp.async.wait_group 1;" ::: "memory")
#define CP_WAIT0()  asm volatile("cp.async.wait_group 0;" ::: "memory")

__device__ __forceinline__ void ldm4(uint32_t* r, uint32_t a){
    asm volatile("ldmatrix.sync.aligned.m8n8.x4.shared.b16 {%0,%1,%2,%3}, [%4];"
        : "=r"(r[0]), "=r"(r[1]), "=r"(r[2]), "=r"(r[3]) : "r"(a));
}
__device__ __forceinline__ void mma_f16(float* c, const uint32_t* a, const uint32_t* b){
    asm volatile("mma.sync.aligned.m16n8k16.row.col.f32.f16.f16.f32 "
        "{%0,%1,%2,%3}, {%4,%5,%6,%7}, {%8,%9}, {%0,%1,%2,%3};"
        : "+f"(c[0]), "+f"(c[1]), "+f"(c[2]), "+f"(c[3])
        : "r"(a[0]), "r"(a[1]), "r"(a[2]), "r"(a[3]), "r"(b[0]), "r"(b[1]));
}

// ---------------- shared GEMM core: tile 128x128, k64 stage, 3-stage, 1 sync/stage ----------------
// D[m][n] = sum_k A[(m0+m)][k] * B[(n0+n)][k].  8 warps = 4(m) x 2(n); warp 32x64.
// EPI 0: fp16 C16[m][n0c+n].            EPI 1: transpose -> Vt[batch][n0c+d][kk] (m0 = global kk row).
// EPI 2: f32 = acc + resid + bias.      EPI 3: exp(scale*acc) fp16 + row partial sums -> esBase.
// EPI 4: fp16 * (1/rowsum from esBase).
#define STAGE_B 32768
#define GSMEM   (3*STAGE_B + 1024)

template<int EPI>
__device__ __forceinline__ void gemm_core(
    const __half* __restrict__ A, int lda,
    const __half* __restrict__ B, int ldb, int Kdim,
    int m0, int n0, int n0c,
    __half* __restrict__ C16, int ldc,
    float* __restrict__ Cf, const float* __restrict__ resid,
    const float* __restrict__ bias, float scale,
    float* __restrict__ esBase, int nblk, char* dynsm)
{
    const uint32_t smbase = smem_u32(dynsm);
    const uint32_t tiles = (smbase + 1023u) & ~1023u;
    const int tid = threadIdx.x, lane = tid & 31, wid = tid >> 5;
    const int wm = wid & 3, wn = wid >> 2;

    float acc[2][8][4];
    #pragma unroll
    for (int i = 0; i < 2; i++)
        #pragma unroll
        for (int j = 0; j < 8; j++)
            #pragma unroll
            for (int k = 0; k < 4; k++) acc[i][j][k] = 0.f;

    const int r_lane = (lane & 7) + ((lane >> 3) & 1) * 8;
    uint32_t aRow[2], aSw[2];
    #pragma unroll
    for (int mt = 0; mt < 2; mt++){
        int m_loc = wm * 32 + mt * 16 + r_lane;
        aRow[mt] = (uint32_t)(m_loc * 128);
        aSw[mt]  = (uint32_t)(m_loc & 7);
    }
    const uint32_t aCk = (lane >> 4) & 1;
    uint32_t bRow[4], bSw[4];
    {
        int n_base = wn * 64 + ((lane >> 4) & 1) * 8 + (lane & 7);
        #pragma unroll
        for (int g = 0; g < 4; g++){
            int n_loc = n_base + g * 16;
            bRow[g] = (uint32_t)(n_loc * 128);
            bSw[g]  = (uint32_t)(n_loc & 7);
        }
    }
    const uint32_t bCk = (lane >> 3) & 1;

    const int C = Kdim >> 6;

    auto load_stage = [&](int c){
        const uint32_t sb = tiles + (c % 3) * STAGE_B;
        const int k0 = c << 6;
        #pragma unroll
        for (int i = 0; i < 4; i++){
            int idx = tid + i * 256;
            int row = idx >> 3, ch = idx & 7;
            uint32_t so = (uint32_t)(row * 128 + ((ch ^ (row & 7)) << 4));
            CP16(sb + so, A + (size_t)(m0 + row) * lda + k0 + ch * 8);
        }
        #pragma unroll
        for (int i = 0; i < 4; i++){
            int idx = tid + i * 256;
            int row = idx >> 3, ch = idx & 7;
            uint32_t so = (uint32_t)(row * 128 + ((ch ^ (row & 7)) << 4));
            CP16(sb + 16384 + so, B + (size_t)(n0 + row) * ldb + k0 + ch * 8);
        }
    };

    load_stage(0); CP_COMMIT();
    load_stage(1); CP_COMMIT();

    for (int c = 0; c < C; c++){
        if (c < C - 1) CP_WAIT1(); else CP_WAIT0();
        __syncthreads();
        if (c + 2 < C){ load_stage(c + 2); CP_COMMIT(); }

        const uint32_t sb = tiles + (c % 3) * STAGE_B;
        #pragma unroll
        for (int ks = 0; ks < 4; ks++){
            uint32_t ah[2][4];
            #pragma unroll
            for (int mt = 0; mt < 2; mt++){
                uint32_t off = aRow[mt] + ((((uint32_t)(2 * ks) + aCk) ^ aSw[mt]) << 4);
                ldm4(ah[mt], sb + off);
            }
            uint32_t bb[8][2];
            #pragma unroll
            for (int g = 0; g < 4; g++){
                uint32_t off = bRow[g] + ((((uint32_t)(2 * ks) + bCk) ^ bSw[g]) << 4);
                uint32_t q[4];
                ldm4(q, sb + 16384 + off);
                bb[2*g][0]=q[0]; bb[2*g][1]=q[1]; bb[2*g+1][0]=q[2]; bb[2*g+1][1]=q[3];
            }
            #pragma unroll
            for (int mt = 0; mt < 2; mt++)
                #pragma unroll
                for (int nf = 0; nf < 8; nf++)
                    mma_f16(acc[mt][nf], ah[mt], bb[nf]);
        }
    }

    const int er = lane >> 2, ec = (lane & 3) * 2;
    if (EPI == 1){
        __half* s = reinterpret_cast<__half*>(dynsm + (tiles - smbase));
        __syncthreads();
        #pragma unroll
        for (int mt = 0; mt < 2; mt++)
            #pragma unroll
            for (int nf = 0; nf < 8; nf++){
                const int dn = wn * 64 + nf * 8 + ec;
                #pragma unroll
                for (int rr = 0; rr < 2; rr++){
                    const int km = wm * 32 + mt * 16 + er + rr * 8;
                    s[(size_t)dn * 136 + km]     = __float2half(acc[mt][nf][rr*2]);
                    s[(size_t)(dn+1) * 136 + km] = __float2half(acc[mt][nf][rr*2+1]);
                }
            }
        __syncthreads();
        const int batch = m0 / KLEN;
        const int kkb   = m0 % KLEN;
        #pragma unroll
        for (int pass = 0; pass < 8; pass++){
            int drow = (tid >> 4) + pass * 16;
            int seg  = tid & 15;
            uint4 v = *reinterpret_cast<const uint4*>(s + (size_t)drow * 136 + seg * 8);
            *reinterpret_cast<uint4*>(C16 + ((size_t)batch * EMBED + n0c + drow) * KLEN + kkb + seg * 8) = v;
        }
        return;
    }
    if (EPI == 3){
        float* rs = reinterpret_cast<float*>(dynsm + (tiles - smbase));
        float rowp[2][2] = {};
        #pragma unroll
        for (int mt = 0; mt < 2; mt++)
            #pragma unroll
            for (int nf = 0; nf < 8; nf++){
                const int n = n0c + wn * 64 + nf * 8 + ec;
                #pragma unroll
                for (int rr = 0; rr < 2; rr++){
                    const int m = m0 + wm * 32 + mt * 16 + er + rr * 8;
                    float e0 = __expf(acc[mt][nf][rr*2]   * scale);
                    float e1 = __expf(acc[mt][nf][rr*2+1] * scale);
                    __half2 hp = __floats2half2_rn(e0, e1);
                    *reinterpret_cast<uint32_t*>(C16 + (size_t)m * ldc + n) = *reinterpret_cast<uint32_t*>(&hp);
                    rowp[mt][rr] += e0 + e1;
                }
            }
        __syncthreads();
        #pragma unroll
        for (int mt = 0; mt < 2; mt++)
            #pragma unroll
            for (int rr = 0; rr < 2; rr++){
                float v = rowp[mt][rr];
                v += __shfl_xor_sync(0xffffffffu, v, 1);
                v += __shfl_xor_sync(0xffffffffu, v, 2);
                if ((lane & 3) == 0){
                    int row = wm * 32 + mt * 16 + rr * 8 + er;
                    rs[wn * 128 + row] = v;
                }
            }
        __syncthreads();
        if (tid < 128)
            esBase[(size_t)(m0 + tid) * NBLK + nblk] = rs[tid] + rs[128 + tid];
        return;
    }
    // EPI 4: compute per-row inverse sums (4 rows per thread, shared by 4 lanes)
    float invr[2][2];
    if (EPI == 4){
        #pragma unroll
        for (int mt = 0; mt < 2; mt++)
            #pragma unroll
            for (int rr = 0; rr < 2; rr++){
                const int m = m0 + wm * 32 + mt * 16 + er + rr * 8;
                const float4* p = reinterpret_cast<const float4*>(esBase + (size_t)m * NBLK);
                float s = 0.f;
                #pragma unroll
                for (int i = 0; i < NBLK/4; i++){
                    float4 v = p[i];
                    s += (v.x + v.y) + (v.z + v.w);
                }
                invr[mt][rr] = 1.f / s;
            }
    }
    #pragma unroll
    for (int mt = 0; mt < 2; mt++)
        #pragma unroll
        for (int nf = 0; nf < 8; nf++){
            const int n = n0c + wn * 64 + nf * 8 + ec;
            #pragma unroll
            for (int rr = 0; rr < 2; rr++){
                const int m = m0 + wm * 32 + mt * 16 + er + rr * 8;
                float v0 = acc[mt][nf][rr * 2], v1 = acc[mt][nf][rr * 2 + 1];
                if (EPI == 4){ v0 *= invr[mt][rr]; v1 *= invr[mt][rr]; }
                if (EPI == 0 || EPI == 4){
                    __half2 hp = __floats2half2_rn(v0, v1);
                    *reinterpret_cast<uint32_t*>(C16 + (size_t)m * ldc + n) = *reinterpret_cast<uint32_t*>(&hp);
                } else {
                    size_t off = (size_t)m * ldc + n;
                    float2 rv = *reinterpret_cast<const float2*>(resid + off);
                    float2 bv = *reinterpret_cast<const float2*>(bias + n);
                    float2 o; o.x = v0 + rv.x + bv.x; o.y = v1 + rv.y + bv.y;
                    *reinterpret_cast<float2*>(Cf + off) = o;
                }
            }
        }
}

// ---------------- fused QKV projection: Q (512 blocks) + KV (2048 blocks) ----------------
__global__ void __launch_bounds__(256, 2)
qkvproj(const __half* __restrict__ x16, const __half* __restrict__ y16,
        const __half* __restrict__ W16,
        __half* __restrict__ Q16, __half* __restrict__ K16, __half* __restrict__ Vt16)
{
    extern __shared__ char dynsm[];
    int id = blockIdx.x;
    const __half* A; const __half* B; __half* C;
    int m0, n0, n0c; bool isV = false;
    if (id < 512){
        m0 = (id >> 2) * 128; n0 = (id & 3) * 128; n0c = n0;
        A = x16; B = W16; C = Q16;                      // Wq
    } else {
        id -= 512;
        m0 = (id >> 3) * 128; n0 = (id & 7) * 128;
        A = y16; B = W16 + (size_t)EMBED * EMBED;       // [Wk;Wv]
        if (n0 < 512){ n0c = n0; C = K16; }
        else { n0c = n0 - 512; C = Vt16; isV = true; }
    }
    if (!isV)
        gemm_core<0>(A, EMBED, B, EMBED, EMBED, m0, n0, n0c, C, EMBED,
                     nullptr, nullptr, nullptr, 1.0f, nullptr, 0, dynsm);
    else
        gemm_core<1>(A, EMBED, B, EMBED, EMBED, m0, n0, n0c, C, 0,
                     nullptr, nullptr, nullptr, 1.0f, nullptr, 0, dynsm);
}

// ---------------- E = exp(sc * Q K^T) + partial sums ----------------
__global__ void __launch_bounds__(256, 2)
gemmE(const __half* __restrict__ Q16, const __half* __restrict__ K16,
      __half* __restrict__ E16, float* __restrict__ Esum, float scale)
{
    extern __shared__ char dynsm[];
    const int b = blockIdx.z;
    gemm_core<3>(Q16 + (size_t)b * QLEN * EMBED, EMBED,
                 K16 + (size_t)b * KLEN * EMBED, EMBED, EMBED,
                 blockIdx.y * 128, blockIdx.x * 128, blockIdx.x * 128,
                 E16 + (size_t)b * QLEN * KLEN, KLEN,
                 nullptr, nullptr, nullptr, scale,
                 Esum + (size_t)b * QLEN * NBLK, blockIdx.x, dynsm);
}

// ---------------- O = (E @ Vt^T) / rowsum ----------------
__global__ void __launch_bounds__(256, 2)
gemmAV(const __half* __restrict__ E16, const __half* __restrict__ Vt16,
       __half* __restrict__ O16, const float* __restrict__ Esum)
{
    extern __shared__ char dynsm[];
    const int b = blockIdx.z;
    gemm_core<4>(E16 + (size_t)b * QLEN * KLEN, KLEN,
                 Vt16 + (size_t)b * EMBED * KLEN, KLEN, KLEN,
                 blockIdx.y * 128, blockIdx.x * 128, blockIdx.x * 128,
                 O16 + (size_t)b * QLEN * EMBED, EMBED,
                 nullptr, nullptr, nullptr, 1.0f,
                 const_cast<float*>(Esum) + (size_t)b * QLEN * NBLK, 0, dynsm);
}

// ---------------- out = x + O @ Wo^T + bo ----------------
__global__ void __launch_bounds__(256, 2)
gemmOut(const __half* __restrict__ O16, const __half* __restrict__ W16,
        float* __restrict__ out, const float* __restrict__ x, const float* __restrict__ bo)
{
    extern __shared__ char dynsm[];
    gemm_core<2>(O16, EMBED, W16 + (size_t)3 * EMBED * EMBED, EMBED, EMBED,
                 blockIdx.y * 128, blockIdx.x * 128, blockIdx.x * 128,
                 nullptr, EMBED, out, x, bo, 1.0f, nullptr, 0, dynsm);
}

// ---------------- one convert kernel for x, y, Wq..Wo ----------------
#define NX (MQ*EMBED)
#define NY (MK*EMBED)
#define NW (EMBED*EMBED)
__global__ void __launch_bounds__(256, 1)
cvtAll(const float* __restrict__ x, const float* __restrict__ y,
       const float* __restrict__ w0, const float* __restrict__ w1,
       const float* __restrict__ w2, const float* __restrict__ w3,
       __half* __restrict__ x16, __half* __restrict__ y16, __half* __restrict__ W16)
{
    int e = (blockIdx.x * 256 + threadIdx.x) * 4;
    const float* src; __half* dst;
    if (e < NX){ src = x + e; dst = x16 + e; }
    else if (e < NX + NY){ int o = e - NX; src = y + o; dst = y16 + o; }
    else {
        int o = e - NX - NY;
        int w = o / NW, r = o % NW;
        src = (w == 0 ? w0 : w == 1 ? w1 : w == 2 ? w2 : w3) + r;
        dst = W16 + (size_t)w * NW + r;
    }
    float4 v = *reinterpret_cast<const float4*>(src);
    __half2 a = __floats2half2_rn(v.x, v.y);
    __half2 b = __floats2half2_rn(v.z, v.w);
    uint2 o;
    o.x = *reinterpret_cast<uint32_t*>(&a);
    o.y = *reinterpret_cast<uint32_t*>(&b);
    *reinterpret_cast<uint2*>(dst) = o;
}

// ---------------- launch ----------------
extern "C" void kernel_launch(void* const* d_in, const int* in_sizes, int n_in,
                              void* d_out, int out_size)
{
    const float* x  = (const float*)d_in[0];
    const float* y  = (const float*)d_in[1];
    const float* Wq = (const float*)d_in[2];
    const float* Wk = (const float*)d_in[3];
    const float* Wv = (const float*)d_in[4];
    const float* Wo = (const float*)d_in[5];
    const float* bo = (const float*)d_in[6];
    float* out = (float*)d_out;

    __half *x16,*y16,*W16,*Q16,*K16,*Vt16,*E16,*O16;
    float *Esum;
    cudaGetSymbolAddress((void**)&x16,  g_x16);
    cudaGetSymbolAddress((void**)&y16,  g_y16);
    cudaGetSymbolAddress((void**)&W16,  g_W16);
    cudaGetSymbolAddress((void**)&Q16,  g_Q16);
    cudaGetSymbolAddress((void**)&K16,  g_K16);
    cudaGetSymbolAddress((void**)&Vt16, g_Vt16);
    cudaGetSymbolAddress((void**)&E16,  g_E16);
    cudaGetSymbolAddress((void**)&O16,  g_O16);
    cudaGetSymbolAddress((void**)&Esum, g_Esum);
    cudaFuncSetAttribute(qkvproj, cudaFuncAttributeMaxDynamicSharedMemorySize, GSMEM);
    cudaFuncSetAttribute(gemmE,   cudaFuncAttributeMaxDynamicSharedMemorySize, GSMEM);
    cudaFuncSetAttribute(gemmAV,  cudaFuncAttributeMaxDynamicSharedMemorySize, GSMEM);
    cudaFuncSetAttribute(gemmOut, cudaFuncAttributeMaxDynamicSharedMemorySize, GSMEM);

    const float sc = 1.0f / sqrtf((float)EMBED);

    cvtAll<<<(NX + NY + 4*NW)/1024, 256>>>(x, y, Wq, Wk, Wv, Wo, x16, y16, W16);
    qkvproj<<<2560, 256, GSMEM>>>(x16, y16, W16, Q16, K16, Vt16);
    gemmE<<<dim3(KLEN/128, QLEN/128, NBATCH), 256, GSMEM>>>(Q16, K16, E16, Esum, sc);
    gemmAV<<<dim3(EMBED/128, QLEN/128, NBATCH), 256, GSMEM>>>(E16, Vt16, O16, Esum);
    gemmOut<<<dim3(EMBED/128, MQ/128, 1), 256, GSMEM>>>(O16, W16, out, x, bo);
}